// round 2
// baseline (speedup 1.0000x reference)
#include <cuda_runtime.h>
#include <stdint.h>

#define SEQ    2048
#define DMODEL 1024
#define NH     16
#define HDIM   64
#define NB     2
#define MROWS  (NB * SEQ)   // 4096

// Scratch (device globals: no allocation allowed in kernel_launch)
__device__ float g_q[MROWS * DMODEL];
__device__ float g_k[MROWS * DMODEL];
__device__ float g_v[MROWS * DMODEL];
__device__ float g_attn[MROWS * DMODEL];

// ---------------------------------------------------------------------------
// C[m][n] = sum_k A[m][k] * W[n][k] + bias[n]
// Tiles: BM=BN=64, BK=16. 256 threads, 4x4 per thread.
// Smem operands stored k-major (transposed) for conflict-free float4 reads.
// ---------------------------------------------------------------------------
__global__ __launch_bounds__(256) void gemm_bias_kernel(
    const float* __restrict__ A, const float* __restrict__ W,
    const float* __restrict__ bias, float* __restrict__ C,
    int M, int N, int K)
{
    __shared__ float As[16 * 64];   // [k][m]
    __shared__ float Ws[16 * 64];   // [k][n]
    const int tid = threadIdx.x;
    const int tx = tid & 15, ty = tid >> 4;
    const int m0 = blockIdx.y << 6, n0 = blockIdx.x << 6;
    const int lrow = tid >> 2;          // 0..63
    const int lc   = (tid & 3) << 2;    // 0,4,8,12

    const float* Ap = A + (size_t)(m0 + lrow) * K + lc;
    const float* Wp = W + (size_t)(n0 + lrow) * K + lc;

    float acc[4][4];
#pragma unroll
    for (int r = 0; r < 4; r++)
#pragma unroll
        for (int c = 0; c < 4; c++) acc[r][c] = 0.f;

    for (int k0 = 0; k0 < K; k0 += 16) {
        float4 av = *(const float4*)(Ap + k0);
        float4 wv = *(const float4*)(Wp + k0);
        As[(lc + 0) * 64 + lrow] = av.x;
        As[(lc + 1) * 64 + lrow] = av.y;
        As[(lc + 2) * 64 + lrow] = av.z;
        As[(lc + 3) * 64 + lrow] = av.w;
        Ws[(lc + 0) * 64 + lrow] = wv.x;
        Ws[(lc + 1) * 64 + lrow] = wv.y;
        Ws[(lc + 2) * 64 + lrow] = wv.z;
        Ws[(lc + 3) * 64 + lrow] = wv.w;
        __syncthreads();
#pragma unroll
        for (int kk = 0; kk < 16; kk++) {
            float4 a = *(const float4*)(As + kk * 64 + ty * 4);
            float4 b = *(const float4*)(Ws + kk * 64 + tx * 4);
            acc[0][0] += a.x * b.x; acc[0][1] += a.x * b.y; acc[0][2] += a.x * b.z; acc[0][3] += a.x * b.w;
            acc[1][0] += a.y * b.x; acc[1][1] += a.y * b.y; acc[1][2] += a.y * b.z; acc[1][3] += a.y * b.w;
            acc[2][0] += a.z * b.x; acc[2][1] += a.z * b.y; acc[2][2] += a.z * b.z; acc[2][3] += a.z * b.w;
            acc[3][0] += a.w * b.x; acc[3][1] += a.w * b.y; acc[3][2] += a.w * b.z; acc[3][3] += a.w * b.w;
        }
        __syncthreads();
    }

    float4 bv = *(const float4*)(bias + n0 + tx * 4);
#pragma unroll
    for (int r = 0; r < 4; r++) {
        int m = m0 + ty * 4 + r;
        float4 ov = make_float4(acc[r][0] + bv.x, acc[r][1] + bv.y,
                                acc[r][2] + bv.z, acc[r][3] + bv.w);
        *(float4*)(C + (size_t)m * N + n0 + tx * 4) = ov;
    }
}

// ---------------------------------------------------------------------------
// Causal flash attention, fp32. 64 queries x 64 keys per block step.
// 256 threads: 16x16 layout, 4x4 microtiles of S and O per thread.
// Smem: QsT [d][qm], KsT [d][key] (reused as P tile), Vs [key][d]. 48KB.
// ---------------------------------------------------------------------------
__global__ __launch_bounds__(256) void attn_kernel(
    const float* __restrict__ Q, const float* __restrict__ Km,
    const float* __restrict__ V, float* __restrict__ O)
{
    __shared__ float QsT[64 * 64];
    __shared__ float KsT[64 * 64];   // reused as Ps after S compute
    __shared__ float Vs[64 * 64];

    const int tid = threadIdx.x;
    const int tx = tid & 15, ty = tid >> 4;
    const int mt = blockIdx.x;               // query tile (0..31)
    const int bh = blockIdx.z;               // b*NH + h
    const int b = bh >> 4, h = bh & 15;
    const int m0 = mt * 64;
    const int hc = h * HDIM;
    const int base = b * SEQ;

    // Load Q tile, transposed into [d][qm]
#pragma unroll
    for (int i = 0; i < 4; i++) {
        int qm = i * 16 + ty;
        float4 qv = *(const float4*)(Q + (size_t)(base + m0 + qm) * DMODEL + hc + tx * 4);
        QsT[(tx * 4 + 0) * 64 + qm] = qv.x;
        QsT[(tx * 4 + 1) * 64 + qm] = qv.y;
        QsT[(tx * 4 + 2) * 64 + qm] = qv.z;
        QsT[(tx * 4 + 3) * 64 + qm] = qv.w;
    }

    float mi[4], li[4], o[4][4];
#pragma unroll
    for (int r = 0; r < 4; r++) {
        mi[r] = -1e30f;
        li[r] = 0.f;
#pragma unroll
        for (int c = 0; c < 4; c++) o[r][c] = 0.f;
    }

    const float scale = 0.125f;   // 1/sqrt(64)

    for (int j = 0; j <= mt; j++) {
        const int n0 = j * 64;
        // Load K (transposed) and V tiles
#pragma unroll
        for (int i = 0; i < 4; i++) {
            int kr = i * 16 + ty;
            float4 kv = *(const float4*)(Km + (size_t)(base + n0 + kr) * DMODEL + hc + tx * 4);
            KsT[(tx * 4 + 0) * 64 + kr] = kv.x;
            KsT[(tx * 4 + 1) * 64 + kr] = kv.y;
            KsT[(tx * 4 + 2) * 64 + kr] = kv.z;
            KsT[(tx * 4 + 3) * 64 + kr] = kv.w;
            float4 vv = *(const float4*)(V + (size_t)(base + n0 + kr) * DMODEL + hc + tx * 4);
            *(float4*)(Vs + kr * 64 + tx * 4) = vv;
        }
        __syncthreads();

        // S = Q K^T
        float s[4][4];
#pragma unroll
        for (int r = 0; r < 4; r++)
#pragma unroll
            for (int c = 0; c < 4; c++) s[r][c] = 0.f;

#pragma unroll 8
        for (int kk = 0; kk < 64; kk++) {
            float4 a = *(const float4*)(QsT + kk * 64 + ty * 4);
            float4 bb = *(const float4*)(KsT + kk * 64 + tx * 4);
            s[0][0] += a.x * bb.x; s[0][1] += a.x * bb.y; s[0][2] += a.x * bb.z; s[0][3] += a.x * bb.w;
            s[1][0] += a.y * bb.x; s[1][1] += a.y * bb.y; s[1][2] += a.y * bb.z; s[1][3] += a.y * bb.w;
            s[2][0] += a.z * bb.x; s[2][1] += a.z * bb.y; s[2][2] += a.z * bb.z; s[2][3] += a.z * bb.w;
            s[3][0] += a.w * bb.x; s[3][1] += a.w * bb.y; s[3][2] += a.w * bb.z; s[3][3] += a.w * bb.w;
        }
        __syncthreads();   // KsT dead; about to be reused as Ps

        // scale + causal mask + online softmax
#pragma unroll
        for (int r = 0; r < 4; r++) {
            const int qrow = m0 + ty * 4 + r;
#pragma unroll
            for (int c = 0; c < 4; c++) {
                float sv = s[r][c] * scale;
                if (n0 + tx * 4 + c > qrow) sv = -1e30f;
                s[r][c] = sv;
            }
            float rm = fmaxf(fmaxf(s[r][0], s[r][1]), fmaxf(s[r][2], s[r][3]));
            rm = fmaxf(rm, __shfl_xor_sync(0xffffffffu, rm, 8));
            rm = fmaxf(rm, __shfl_xor_sync(0xffffffffu, rm, 4));
            rm = fmaxf(rm, __shfl_xor_sync(0xffffffffu, rm, 2));
            rm = fmaxf(rm, __shfl_xor_sync(0xffffffffu, rm, 1));
            float mnew = fmaxf(mi[r], rm);
            float alpha = __expf(mi[r] - mnew);
            mi[r] = mnew;
            float rs = 0.f;
#pragma unroll
            for (int c = 0; c < 4; c++) {
                float p = __expf(s[r][c] - mnew);
                s[r][c] = p;
                rs += p;
            }
            rs += __shfl_xor_sync(0xffffffffu, rs, 8);
            rs += __shfl_xor_sync(0xffffffffu, rs, 4);
            rs += __shfl_xor_sync(0xffffffffu, rs, 2);
            rs += __shfl_xor_sync(0xffffffffu, rs, 1);
            li[r] = li[r] * alpha + rs;
#pragma unroll
            for (int c = 0; c < 4; c++) o[r][c] *= alpha;
        }

        // Store P tile into KsT region
#pragma unroll
        for (int r = 0; r < 4; r++) {
            float4 pv = make_float4(s[r][0], s[r][1], s[r][2], s[r][3]);
            *(float4*)(KsT + (ty * 4 + r) * 64 + tx * 4) = pv;
        }
        __syncthreads();

        // O += P V
#pragma unroll 8
        for (int t = 0; t < 64; t++) {
            float4 vv = *(const float4*)(Vs + t * 64 + tx * 4);
#pragma unroll
            for (int r = 0; r < 4; r++) {
                float p = KsT[(ty * 4 + r) * 64 + t];
                o[r][0] += p * vv.x;
                o[r][1] += p * vv.y;
                o[r][2] += p * vv.z;
                o[r][3] += p * vv.w;
            }
        }
        __syncthreads();   // before next tile overwrites KsT/Vs
    }

    // Normalize and write out in [B,S,(h d)] layout
#pragma unroll
    for (int r = 0; r < 4; r++) {
        int row = m0 + ty * 4 + r;
        float inv = 1.f / li[r];
        float4 ov = make_float4(o[r][0] * inv, o[r][1] * inv,
                                o[r][2] * inv, o[r][3] * inv);
        *(float4*)(O + (size_t)(base + row) * DMODEL + hc + tx * 4) = ov;
    }
}

// ---------------------------------------------------------------------------
extern "C" void kernel_launch(void* const* d_in, const int* in_sizes, int n_in,
                              void* d_out, int out_size)
{
    const float* X  = (const float*)d_in[0];
    const float* Wq = (const float*)d_in[1];
    const float* bq = (const float*)d_in[2];
    const float* Wk = (const float*)d_in[3];
    const float* bk = (const float*)d_in[4];
    const float* Wv = (const float*)d_in[5];
    const float* bv = (const float*)d_in[6];
    const float* Wo = (const float*)d_in[7];
    const float* bo = (const float*)d_in[8];
    float* Y = (float*)d_out;

    float *q, *k, *v, *a;
    cudaGetSymbolAddress((void**)&q, g_q);
    cudaGetSymbolAddress((void**)&k, g_k);
    cudaGetSymbolAddress((void**)&v, g_v);
    cudaGetSymbolAddress((void**)&a, g_attn);

    dim3 gproj(DMODEL / 64, MROWS / 64);   // (16, 64)
    gemm_bias_kernel<<<gproj, 256>>>(X, Wq, bq, q, MROWS, DMODEL, DMODEL);
    gemm_bias_kernel<<<gproj, 256>>>(X, Wk, bk, k, MROWS, DMODEL, DMODEL);
    gemm_bias_kernel<<<gproj, 256>>>(X, Wv, bv, v, MROWS, DMODEL, DMODEL);

    dim3 gattn(SEQ / 64, 1, NB * NH);      // (32, 1, 32)
    attn_kernel<<<gattn, 256>>>(q, k, v, a);

    gemm_bias_kernel<<<gproj, 256>>>(a, Wo, bo, Y, MROWS, DMODEL, DMODEL);
}

// round 4
// speedup vs baseline: 1.6147x; 1.6147x over previous
#include <cuda_runtime.h>
#include <cuda_bf16.h>
#include <stdint.h>

#define SEQ    2048
#define DMODEL 1024
#define NH     16
#define HDIM   64
#define NB     2
#define MROWS  (NB * SEQ)   // 4096
#define GK     DMODEL

// Scratch (device globals: no allocation allowed in kernel_launch)
__device__ float g_q[MROWS * DMODEL];
__device__ float g_k[MROWS * DMODEL];
__device__ float g_v[MROWS * DMODEL];
__device__ float g_attn[MROWS * DMODEL];
__device__ __nv_bfloat16 g_xh[MROWS * DMODEL];
__device__ __nv_bfloat16 g_xl[MROWS * DMODEL];
__device__ __nv_bfloat16 g_wh[4 * DMODEL * DMODEL];
__device__ __nv_bfloat16 g_wl[4 * DMODEL * DMODEL];
__device__ __nv_bfloat16 g_ah[MROWS * DMODEL];
__device__ __nv_bfloat16 g_al[MROWS * DMODEL];

// ---------------------------------------------------------------------------
// helpers (all baseline PTX: sm_80-class, no 'a'-suffix features)
// ---------------------------------------------------------------------------
__device__ __forceinline__ uint32_t smem_u32(const void* p) {
    uint32_t a;
    asm("{ .reg .u64 t; cvta.to.shared.u64 t, %1; cvt.u32.u64 %0, t; }"
        : "=r"(a) : "l"(p));
    return a;
}

__device__ __forceinline__ void cp16(uint32_t s, const void* g) {
    asm volatile("cp.async.cg.shared.global [%0], [%1], 16;" :: "r"(s), "l"(g));
}

__device__ __forceinline__ void ldsm4(uint32_t* r, uint32_t a) {
    asm volatile("ldmatrix.sync.aligned.m8n8.x4.shared.b16 {%0,%1,%2,%3}, [%4];"
                 : "=r"(r[0]), "=r"(r[1]), "=r"(r[2]), "=r"(r[3]) : "r"(a));
}

__device__ __forceinline__ void mma_bf16(float* d, const uint32_t* a,
                                         uint32_t b0, uint32_t b1) {
    asm volatile(
        "mma.sync.aligned.m16n8k16.row.col.f32.bf16.bf16.f32 "
        "{%0,%1,%2,%3}, {%4,%5,%6,%7}, {%8,%9}, {%0,%1,%2,%3};"
        : "+f"(d[0]), "+f"(d[1]), "+f"(d[2]), "+f"(d[3])
        : "r"(a[0]), "r"(a[1]), "r"(a[2]), "r"(a[3]), "r"(b0), "r"(b1));
}

// ---------------------------------------------------------------------------
// fp32 -> (bf16 hi, bf16 residual) split, vectorized by 4
// ---------------------------------------------------------------------------
__global__ __launch_bounds__(256) void split_kernel(
    const float* __restrict__ in, __nv_bfloat16* __restrict__ hi,
    __nv_bfloat16* __restrict__ lo, int n4)
{
    int i = blockIdx.x * blockDim.x + threadIdx.x;
    if (i >= n4) return;
    float4 v = ((const float4*)in)[i];
    __nv_bfloat162 h0 = __floats2bfloat162_rn(v.x, v.y);
    __nv_bfloat162 h1 = __floats2bfloat162_rn(v.z, v.w);
    __nv_bfloat162 l0 = __floats2bfloat162_rn(v.x - __bfloat162float(h0.x),
                                              v.y - __bfloat162float(h0.y));
    __nv_bfloat162 l1 = __floats2bfloat162_rn(v.z - __bfloat162float(h1.x),
                                              v.w - __bfloat162float(h1.y));
    ((__nv_bfloat162*)hi)[2 * i]     = h0;
    ((__nv_bfloat162*)hi)[2 * i + 1] = h1;
    ((__nv_bfloat162*)lo)[2 * i]     = l0;
    ((__nv_bfloat162*)lo)[2 * i + 1] = l1;
}

// ---------------------------------------------------------------------------
// HMMA GEMM: Out[m][n] = sum_k A[m][k]*W[n][k] + bias[n]
// A,W given as bf16 hi/lo pairs; split-3 accumulation (hh + hl + lh) in fp32.
// CTA 128x128, BK=64, cp.async double buffer, XOR-swizzled smem, ldmatrix.
// blockIdx.z selects weight set (packed in Whb/Wlb) + bias + output.
// Dyn smem per stage (64KB): Ah(16K) Al(16K) Wh(16K) Wl(16K); 2 stages.
// ---------------------------------------------------------------------------
#define GEMM_SMEM (2 * 65536)

__global__ __launch_bounds__(256, 1) void gemm_mma(
    const __nv_bfloat16* __restrict__ Ah, const __nv_bfloat16* __restrict__ Al,
    const __nv_bfloat16* __restrict__ Whb, const __nv_bfloat16* __restrict__ Wlb,
    const float* __restrict__ bias0, const float* __restrict__ bias1,
    const float* __restrict__ bias2,
    float* __restrict__ out0, float* __restrict__ out1, float* __restrict__ out2)
{
    extern __shared__ char smem[];
    const int tid = threadIdx.x;
    const int z = blockIdx.z;
    const __nv_bfloat16* Wh = Whb + (size_t)z * GK * GK;
    const __nv_bfloat16* Wl = Wlb + (size_t)z * GK * GK;
    const float* bias = (z == 0) ? bias0 : ((z == 1) ? bias1 : bias2);
    float* Out        = (z == 0) ? out0  : ((z == 1) ? out1  : out2);
    const int m0 = blockIdx.y * 128, n0 = blockIdx.x * 128;

    const uint32_t sb = smem_u32(smem);
    const int lane = tid & 31, warp = tid >> 5;
    const int wm = warp & 1, wn = warp >> 1;   // warp tile 64x32

    // loader mapping: 2 threads per row, 4 16B-chunks each
    const int lr = tid >> 1;
    const int lh = (tid & 1) * 4;
    const __nv_bfloat16* gAh = Ah + (size_t)(m0 + lr) * GK + lh * 8;
    const __nv_bfloat16* gAl = Al + (size_t)(m0 + lr) * GK + lh * 8;
    const __nv_bfloat16* gWh = Wh + (size_t)(n0 + lr) * GK + lh * 8;
    const __nv_bfloat16* gWl = Wl + (size_t)(n0 + lr) * GK + lh * 8;
    const uint32_t lrow = (uint32_t)(lr * 128);
    const int lswz = lr & 7;

    // ldmatrix lane decode
    const int arow = (lane & 7) + ((lane >> 3) & 1) * 8;  // A: row within 16
    const int akb  = lane >> 4;                            // A: k sub-chunk
    const int bnof = ((lane >> 4) << 3) + (lane & 7);      // B: n within 16
    const int bkb  = (lane >> 3) & 1;                      // B: k sub-chunk

    float acc[4][4][4];
#pragma unroll
    for (int i = 0; i < 4; i++)
#pragma unroll
        for (int j = 0; j < 4; j++)
#pragma unroll
            for (int t = 0; t < 4; t++) acc[i][j][t] = 0.f;

    // prologue: stage 0
    {
        uint32_t base = sb + lrow;
#pragma unroll
        for (int j = 0; j < 4; ++j) {
            uint32_t sw = (uint32_t)(((lh + j) ^ lswz) * 16);
            cp16(base + sw,         gAh + j * 8);
            cp16(base + 16384 + sw, gAl + j * 8);
            cp16(base + 32768 + sw, gWh + j * 8);
            cp16(base + 49152 + sw, gWl + j * 8);
        }
        asm volatile("cp.async.commit_group;");
    }

    for (int c = 0; c < GK / 64; ++c) {
        if (c + 1 < GK / 64) {
            const int k0 = (c + 1) * 64;
            uint32_t base = sb + ((c + 1) & 1) * 65536 + lrow;
#pragma unroll
            for (int j = 0; j < 4; ++j) {
                uint32_t sw = (uint32_t)(((lh + j) ^ lswz) * 16);
                cp16(base + sw,         gAh + k0 + j * 8);
                cp16(base + 16384 + sw, gAl + k0 + j * 8);
                cp16(base + 32768 + sw, gWh + k0 + j * 8);
                cp16(base + 49152 + sw, gWl + k0 + j * 8);
            }
            asm volatile("cp.async.commit_group;");
            asm volatile("cp.async.wait_group 1;");
        } else {
            asm volatile("cp.async.commit_group;");
            asm volatile("cp.async.wait_group 0;");
        }
        __syncthreads();

        const uint32_t aH = sb + (c & 1) * 65536;
        const uint32_t aL = aH + 16384;
        const uint32_t wH = aH + 32768;
        const uint32_t wL = aH + 49152;

#pragma unroll
        for (int kk = 0; kk < 4; ++kk) {
            // B fragments: two n-block pairs (hi and lo)
            uint32_t bh[2][4], bl[2][4];
#pragma unroll
            for (int nip = 0; nip < 2; ++nip) {
                int n = wn * 32 + nip * 16 + bnof;
                uint32_t off = (uint32_t)(n * 128 + (((kk * 2 + bkb) ^ (n & 7)) * 16));
                ldsm4(bh[nip], wH + off);
                ldsm4(bl[nip], wL + off);
            }
#pragma unroll
            for (int mi = 0; mi < 4; ++mi) {
                int r = wm * 64 + mi * 16 + arow;
                uint32_t off = (uint32_t)(r * 128 + (((kk * 2 + akb) ^ (r & 7)) * 16));
                uint32_t ah[4], al[4];
                ldsm4(ah, aH + off);
                ldsm4(al, aL + off);
#pragma unroll
                for (int ni = 0; ni < 4; ++ni) {
                    const int nip = ni >> 1, q = (ni & 1) * 2;
                    mma_bf16(acc[mi][ni], ah, bh[nip][q], bh[nip][q + 1]);
                    mma_bf16(acc[mi][ni], ah, bl[nip][q], bl[nip][q + 1]);
                    mma_bf16(acc[mi][ni], al, bh[nip][q], bh[nip][q + 1]);
                }
            }
        }
        __syncthreads();
    }

    // epilogue: bias + store fp32
#pragma unroll
    for (int mi = 0; mi < 4; ++mi) {
        const int r0 = m0 + wm * 64 + mi * 16 + (lane >> 2);
#pragma unroll
        for (int ni = 0; ni < 4; ++ni) {
            const int c0 = n0 + wn * 32 + ni * 8 + (lane & 3) * 2;
            const float bv0 = bias[c0], bv1 = bias[c0 + 1];
            Out[(size_t)r0 * GK + c0]           = acc[mi][ni][0] + bv0;
            Out[(size_t)r0 * GK + c0 + 1]       = acc[mi][ni][1] + bv1;
            Out[(size_t)(r0 + 8) * GK + c0]     = acc[mi][ni][2] + bv0;
            Out[(size_t)(r0 + 8) * GK + c0 + 1] = acc[mi][ni][3] + bv1;
        }
    }
}

// ---------------------------------------------------------------------------
// Causal flash attention, fp32 (unchanged, verified 690us).
// ---------------------------------------------------------------------------
__global__ __launch_bounds__(256) void attn_kernel(
    const float* __restrict__ Q, const float* __restrict__ Km,
    const float* __restrict__ V, float* __restrict__ O)
{
    __shared__ float QsT[64 * 64];
    __shared__ float KsT[64 * 64];
    __shared__ float Vs[64 * 64];

    const int tid = threadIdx.x;
    const int tx = tid & 15, ty = tid >> 4;
    const int mt = blockIdx.x;
    const int bh = blockIdx.z;
    const int b = bh >> 4, h = bh & 15;
    const int m0 = mt * 64;
    const int hc = h * HDIM;
    const int base = b * SEQ;

#pragma unroll
    for (int i = 0; i < 4; i++) {
        int qm = i * 16 + ty;
        float4 qv = *(const float4*)(Q + (size_t)(base + m0 + qm) * DMODEL + hc + tx * 4);
        QsT[(tx * 4 + 0) * 64 + qm] = qv.x;
        QsT[(tx * 4 + 1) * 64 + qm] = qv.y;
        QsT[(tx * 4 + 2) * 64 + qm] = qv.z;
        QsT[(tx * 4 + 3) * 64 + qm] = qv.w;
    }

    float mi[4], li[4], o[4][4];
#pragma unroll
    for (int r = 0; r < 4; r++) {
        mi[r] = -1e30f;
        li[r] = 0.f;
#pragma unroll
        for (int c = 0; c < 4; c++) o[r][c] = 0.f;
    }

    const float scale = 0.125f;

    for (int j = 0; j <= mt; j++) {
        const int n0 = j * 64;
#pragma unroll
        for (int i = 0; i < 4; i++) {
            int kr = i * 16 + ty;
            float4 kv = *(const float4*)(Km + (size_t)(base + n0 + kr) * DMODEL + hc + tx * 4);
            KsT[(tx * 4 + 0) * 64 + kr] = kv.x;
            KsT[(tx * 4 + 1) * 64 + kr] = kv.y;
            KsT[(tx * 4 + 2) * 64 + kr] = kv.z;
            KsT[(tx * 4 + 3) * 64 + kr] = kv.w;
            float4 vv = *(const float4*)(V + (size_t)(base + n0 + kr) * DMODEL + hc + tx * 4);
            *(float4*)(Vs + kr * 64 + tx * 4) = vv;
        }
        __syncthreads();

        float s[4][4];
#pragma unroll
        for (int r = 0; r < 4; r++)
#pragma unroll
            for (int c = 0; c < 4; c++) s[r][c] = 0.f;

#pragma unroll 8
        for (int kk = 0; kk < 64; kk++) {
            float4 a = *(const float4*)(QsT + kk * 64 + ty * 4);
            float4 bb = *(const float4*)(KsT + kk * 64 + tx * 4);
            s[0][0] += a.x * bb.x; s[0][1] += a.x * bb.y; s[0][2] += a.x * bb.z; s[0][3] += a.x * bb.w;
            s[1][0] += a.y * bb.x; s[1][1] += a.y * bb.y; s[1][2] += a.y * bb.z; s[1][3] += a.y * bb.w;
            s[2][0] += a.z * bb.x; s[2][1] += a.z * bb.y; s[2][2] += a.z * bb.z; s[2][3] += a.z * bb.w;
            s[3][0] += a.w * bb.x; s[3][1] += a.w * bb.y; s[3][2] += a.w * bb.z; s[3][3] += a.w * bb.w;
        }
        __syncthreads();

#pragma unroll
        for (int r = 0; r < 4; r++) {
            const int qrow = m0 + ty * 4 + r;
#pragma unroll
            for (int c = 0; c < 4; c++) {
                float sv = s[r][c] * scale;
                if (n0 + tx * 4 + c > qrow) sv = -1e30f;
                s[r][c] = sv;
            }
            float rm = fmaxf(fmaxf(s[r][0], s[r][1]), fmaxf(s[r][2], s[r][3]));
            rm = fmaxf(rm, __shfl_xor_sync(0xffffffffu, rm, 8));
            rm = fmaxf(rm, __shfl_xor_sync(0xffffffffu, rm, 4));
            rm = fmaxf(rm, __shfl_xor_sync(0xffffffffu, rm, 2));
            rm = fmaxf(rm, __shfl_xor_sync(0xffffffffu, rm, 1));
            float mnew = fmaxf(mi[r], rm);
            float alpha = __expf(mi[r] - mnew);
            mi[r] = mnew;
            float rs = 0.f;
#pragma unroll
            for (int c = 0; c < 4; c++) {
                float p = __expf(s[r][c] - mnew);
                s[r][c] = p;
                rs += p;
            }
            rs += __shfl_xor_sync(0xffffffffu, rs, 8);
            rs += __shfl_xor_sync(0xffffffffu, rs, 4);
            rs += __shfl_xor_sync(0xffffffffu, rs, 2);
            rs += __shfl_xor_sync(0xffffffffu, rs, 1);
            li[r] = li[r] * alpha + rs;
#pragma unroll
            for (int c = 0; c < 4; c++) o[r][c] *= alpha;
        }

#pragma unroll
        for (int r = 0; r < 4; r++) {
            float4 pv = make_float4(s[r][0], s[r][1], s[r][2], s[r][3]);
            *(float4*)(KsT + (ty * 4 + r) * 64 + tx * 4) = pv;
        }
        __syncthreads();

#pragma unroll 8
        for (int t = 0; t < 64; t++) {
            float4 vv = *(const float4*)(Vs + t * 64 + tx * 4);
#pragma unroll
            for (int r = 0; r < 4; r++) {
                float p = KsT[(ty * 4 + r) * 64 + t];
                o[r][0] += p * vv.x;
                o[r][1] += p * vv.y;
                o[r][2] += p * vv.z;
                o[r][3] += p * vv.w;
            }
        }
        __syncthreads();
    }

#pragma unroll
    for (int r = 0; r < 4; r++) {
        int row = m0 + ty * 4 + r;
        float inv = 1.f / li[r];
        float4 ov = make_float4(o[r][0] * inv, o[r][1] * inv,
                                o[r][2] * inv, o[r][3] * inv);
        *(float4*)(O + (size_t)(base + row) * DMODEL + hc + tx * 4) = ov;
    }
}

// ---------------------------------------------------------------------------
extern "C" void kernel_launch(void* const* d_in, const int* in_sizes, int n_in,
                              void* d_out, int out_size)
{
    const float* X  = (const float*)d_in[0];
    const float* Wq = (const float*)d_in[1];
    const float* bq = (const float*)d_in[2];
    const float* Wk = (const float*)d_in[3];
    const float* bk = (const float*)d_in[4];
    const float* Wv = (const float*)d_in[5];
    const float* bv = (const float*)d_in[6];
    const float* Wo = (const float*)d_in[7];
    const float* bo = (const float*)d_in[8];
    float* Y = (float*)d_out;

    float *q, *k, *v, *a;
    __nv_bfloat16 *xh, *xl, *wh, *wl, *ah, *al;
    cudaGetSymbolAddress((void**)&q, g_q);
    cudaGetSymbolAddress((void**)&k, g_k);
    cudaGetSymbolAddress((void**)&v, g_v);
    cudaGetSymbolAddress((void**)&a, g_attn);
    cudaGetSymbolAddress((void**)&xh, g_xh);
    cudaGetSymbolAddress((void**)&xl, g_xl);
    cudaGetSymbolAddress((void**)&wh, g_wh);
    cudaGetSymbolAddress((void**)&wl, g_wl);
    cudaGetSymbolAddress((void**)&ah, g_ah);
    cudaGetSymbolAddress((void**)&al, g_al);

    cudaFuncSetAttribute(gemm_mma,
                         cudaFuncAttributeMaxDynamicSharedMemorySize, GEMM_SMEM);

    const int WN4 = DMODEL * DMODEL / 4;   // 262144
    // split X and the four weight matrices into bf16 hi/lo
    split_kernel<<<MROWS * DMODEL / 4 / 256, 256>>>(X, xh, xl, MROWS * DMODEL / 4);
    split_kernel<<<WN4 / 256, 256>>>(Wq, wh + 0 * DMODEL * DMODEL, wl + 0 * DMODEL * DMODEL, WN4);
    split_kernel<<<WN4 / 256, 256>>>(Wk, wh + 1 * DMODEL * DMODEL, wl + 1 * DMODEL * DMODEL, WN4);
    split_kernel<<<WN4 / 256, 256>>>(Wv, wh + 2 * DMODEL * DMODEL, wl + 2 * DMODEL * DMODEL, WN4);
    split_kernel<<<WN4 / 256, 256>>>(Wo, wh + 3 * DMODEL * DMODEL, wl + 3 * DMODEL * DMODEL, WN4);

    // fused QKV projections (HMMA)
    dim3 gqkv(DMODEL / 128, MROWS / 128, 3);   // (8, 32, 3)
    gemm_mma<<<gqkv, 256, GEMM_SMEM>>>(xh, xl, wh, wl, bq, bk, bv, q, k, v);

    // attention (fp32)
    dim3 gattn(SEQ / 64, 1, NB * NH);
    attn_kernel<<<gattn, 256>>>(q, k, v, a);

    // split attention output, then O projection
    split_kernel<<<MROWS * DMODEL / 4 / 256, 256>>>(a, ah, al, MROWS * DMODEL / 4);
    dim3 go(DMODEL / 128, MROWS / 128, 1);
    gemm_mma<<<go, 256, GEMM_SMEM>>>(ah, al, wh + 3 * DMODEL * DMODEL,
                                     wl + 3 * DMODEL * DMODEL,
                                     bo, bo, bo, Y, Y, Y);
}

// round 5
// speedup vs baseline: 3.0985x; 1.9189x over previous
#include <cuda_runtime.h>
#include <cuda_bf16.h>
#include <cuda_fp16.h>
#include <stdint.h>

#define SEQ    2048
#define DMODEL 1024
#define NH     16
#define HDIM   64
#define NB     2
#define MROWS  (NB * SEQ)   // 4096
#define GK     DMODEL

#define QSCALE 0.18033688011112042f   // 0.125 * log2(e)

// Scratch (device globals: no allocation allowed in kernel_launch)
__device__ __nv_bfloat16 g_xh[MROWS * DMODEL];
__device__ __nv_bfloat16 g_xl[MROWS * DMODEL];
__device__ __nv_bfloat16 g_wh[4 * DMODEL * DMODEL];
__device__ __nv_bfloat16 g_wl[4 * DMODEL * DMODEL];
__device__ __half g_qh[MROWS * DMODEL];
__device__ __half g_ql[MROWS * DMODEL];
__device__ __half g_kh[MROWS * DMODEL];
__device__ __half g_kl[MROWS * DMODEL];
__device__ __half g_vh[MROWS * DMODEL];
__device__ __half g_vl[MROWS * DMODEL];
__device__ __nv_bfloat16 g_ah[MROWS * DMODEL];
__device__ __nv_bfloat16 g_al[MROWS * DMODEL];

// ---------------------------------------------------------------------------
// helpers (all baseline PTX: sm_80-class, no 'a'-suffix features)
// ---------------------------------------------------------------------------
__device__ __forceinline__ uint32_t smem_u32(const void* p) {
    uint32_t a;
    asm("{ .reg .u64 t; cvta.to.shared.u64 t, %1; cvt.u32.u64 %0, t; }"
        : "=r"(a) : "l"(p));
    return a;
}

__device__ __forceinline__ void cp16(uint32_t s, const void* g) {
    asm volatile("cp.async.cg.shared.global [%0], [%1], 16;" :: "r"(s), "l"(g));
}

__device__ __forceinline__ void ldsm4(uint32_t* r, uint32_t a) {
    asm volatile("ldmatrix.sync.aligned.m8n8.x4.shared.b16 {%0,%1,%2,%3}, [%4];"
                 : "=r"(r[0]), "=r"(r[1]), "=r"(r[2]), "=r"(r[3]) : "r"(a));
}

__device__ __forceinline__ void ldsm4t(uint32_t* r, uint32_t a) {
    asm volatile("ldmatrix.sync.aligned.m8n8.x4.trans.shared.b16 {%0,%1,%2,%3}, [%4];"
                 : "=r"(r[0]), "=r"(r[1]), "=r"(r[2]), "=r"(r[3]) : "r"(a));
}

__device__ __forceinline__ void mma_bf16(float* d, const uint32_t* a,
                                         uint32_t b0, uint32_t b1) {
    asm volatile(
        "mma.sync.aligned.m16n8k16.row.col.f32.bf16.bf16.f32 "
        "{%0,%1,%2,%3}, {%4,%5,%6,%7}, {%8,%9}, {%0,%1,%2,%3};"
        : "+f"(d[0]), "+f"(d[1]), "+f"(d[2]), "+f"(d[3])
        : "r"(a[0]), "r"(a[1]), "r"(a[2]), "r"(a[3]), "r"(b0), "r"(b1));
}

__device__ __forceinline__ void mma_f16(float* d, const uint32_t* a,
                                        uint32_t b0, uint32_t b1) {
    asm volatile(
        "mma.sync.aligned.m16n8k16.row.col.f32.f16.f16.f32 "
        "{%0,%1,%2,%3}, {%4,%5,%6,%7}, {%8,%9}, {%0,%1,%2,%3};"
        : "+f"(d[0]), "+f"(d[1]), "+f"(d[2]), "+f"(d[3])
        : "r"(a[0]), "r"(a[1]), "r"(a[2]), "r"(a[3]), "r"(b0), "r"(b1));
}

__device__ __forceinline__ float ex2f(float x) {
    float r;
    asm("ex2.approx.f32 %0, %1;" : "=f"(r) : "f"(x));
    return r;
}

// pack (lo,hi) to f16x2 then 2^x elementwise
__device__ __forceinline__ uint32_t exp2_f16x2(float lo, float hi) {
    uint32_t p, r;
    asm("cvt.rn.f16x2.f32 %0, %1, %2;" : "=r"(p) : "f"(hi), "f"(lo));
    asm("ex2.approx.f16x2 %0, %1;" : "=r"(r) : "r"(p));
    return r;
}

// ---------------------------------------------------------------------------
// fp32 -> (bf16 hi, bf16 residual) split, vectorized by 4
// ---------------------------------------------------------------------------
__global__ __launch_bounds__(256) void split_kernel(
    const float* __restrict__ in, __nv_bfloat16* __restrict__ hi,
    __nv_bfloat16* __restrict__ lo, int n4)
{
    int i = blockIdx.x * blockDim.x + threadIdx.x;
    if (i >= n4) return;
    float4 v = ((const float4*)in)[i];
    __nv_bfloat162 h0 = __floats2bfloat162_rn(v.x, v.y);
    __nv_bfloat162 h1 = __floats2bfloat162_rn(v.z, v.w);
    __nv_bfloat162 l0 = __floats2bfloat162_rn(v.x - __bfloat162float(h0.x),
                                              v.y - __bfloat162float(h0.y));
    __nv_bfloat162 l1 = __floats2bfloat162_rn(v.z - __bfloat162float(h1.x),
                                              v.w - __bfloat162float(h1.y));
    ((__nv_bfloat162*)hi)[2 * i]     = h0;
    ((__nv_bfloat162*)hi)[2 * i + 1] = h1;
    ((__nv_bfloat162*)lo)[2 * i]     = l0;
    ((__nv_bfloat162*)lo)[2 * i + 1] = l1;
}

// ---------------------------------------------------------------------------
// HMMA GEMM: Out[m][n] = sum_k A[m][k]*W[n][k] + bias[n]
// OM==0: fp32 output.  OM==1: fp16 hi/lo split output (scale applied for z==0).
// ---------------------------------------------------------------------------
#define GEMM_SMEM (2 * 65536)

template<int OM>
__global__ __launch_bounds__(256, 1) void gemm_mma(
    const __nv_bfloat16* __restrict__ Ah, const __nv_bfloat16* __restrict__ Al,
    const __nv_bfloat16* __restrict__ Whb, const __nv_bfloat16* __restrict__ Wlb,
    const float* __restrict__ bias0, const float* __restrict__ bias1,
    const float* __restrict__ bias2,
    float* __restrict__ out0,
    __half* __restrict__ sh0, __half* __restrict__ sl0,
    __half* __restrict__ sh1, __half* __restrict__ sl1,
    __half* __restrict__ sh2, __half* __restrict__ sl2,
    float scale0)
{
    extern __shared__ char smem[];
    const int tid = threadIdx.x;
    const int z = blockIdx.z;
    const __nv_bfloat16* Wh = Whb + (size_t)z * GK * GK;
    const __nv_bfloat16* Wl = Wlb + (size_t)z * GK * GK;
    const float* bias = (z == 0) ? bias0 : ((z == 1) ? bias1 : bias2);
    const int m0 = blockIdx.y * 128, n0 = blockIdx.x * 128;

    const uint32_t sb = smem_u32(smem);
    const int lane = tid & 31, warp = tid >> 5;
    const int wm = warp & 1, wn = warp >> 1;

    const int lr = tid >> 1;
    const int lh = (tid & 1) * 4;
    const __nv_bfloat16* gAh = Ah + (size_t)(m0 + lr) * GK + lh * 8;
    const __nv_bfloat16* gAl = Al + (size_t)(m0 + lr) * GK + lh * 8;
    const __nv_bfloat16* gWh = Wh + (size_t)(n0 + lr) * GK + lh * 8;
    const __nv_bfloat16* gWl = Wl + (size_t)(n0 + lr) * GK + lh * 8;
    const uint32_t lrow = (uint32_t)(lr * 128);
    const int lswz = lr & 7;

    const int arow = (lane & 7) + ((lane >> 3) & 1) * 8;
    const int akb  = lane >> 4;
    const int bnof = ((lane >> 4) << 3) + (lane & 7);
    const int bkb  = (lane >> 3) & 1;

    float acc[4][4][4];
#pragma unroll
    for (int i = 0; i < 4; i++)
#pragma unroll
        for (int j = 0; j < 4; j++)
#pragma unroll
            for (int t = 0; t < 4; t++) acc[i][j][t] = 0.f;

    {
        uint32_t base = sb + lrow;
#pragma unroll
        for (int j = 0; j < 4; ++j) {
            uint32_t sw = (uint32_t)(((lh + j) ^ lswz) * 16);
            cp16(base + sw,         gAh + j * 8);
            cp16(base + 16384 + sw, gAl + j * 8);
            cp16(base + 32768 + sw, gWh + j * 8);
            cp16(base + 49152 + sw, gWl + j * 8);
        }
        asm volatile("cp.async.commit_group;");
    }

    for (int c = 0; c < GK / 64; ++c) {
        if (c + 1 < GK / 64) {
            const int k0 = (c + 1) * 64;
            uint32_t base = sb + ((c + 1) & 1) * 65536 + lrow;
#pragma unroll
            for (int j = 0; j < 4; ++j) {
                uint32_t sw = (uint32_t)(((lh + j) ^ lswz) * 16);
                cp16(base + sw,         gAh + k0 + j * 8);
                cp16(base + 16384 + sw, gAl + k0 + j * 8);
                cp16(base + 32768 + sw, gWh + k0 + j * 8);
                cp16(base + 49152 + sw, gWl + k0 + j * 8);
            }
            asm volatile("cp.async.commit_group;");
            asm volatile("cp.async.wait_group 1;");
        } else {
            asm volatile("cp.async.commit_group;");
            asm volatile("cp.async.wait_group 0;");
        }
        __syncthreads();

        const uint32_t aH = sb + (c & 1) * 65536;
        const uint32_t aL = aH + 16384;
        const uint32_t wH = aH + 32768;
        const uint32_t wL = aH + 49152;

#pragma unroll
        for (int kk = 0; kk < 4; ++kk) {
            uint32_t bh[2][4], bl[2][4];
#pragma unroll
            for (int nip = 0; nip < 2; ++nip) {
                int n = wn * 32 + nip * 16 + bnof;
                uint32_t off = (uint32_t)(n * 128 + (((kk * 2 + bkb) ^ (n & 7)) * 16));
                ldsm4(bh[nip], wH + off);
                ldsm4(bl[nip], wL + off);
            }
#pragma unroll
            for (int mi = 0; mi < 4; ++mi) {
                int r = wm * 64 + mi * 16 + arow;
                uint32_t off = (uint32_t)(r * 128 + (((kk * 2 + akb) ^ (r & 7)) * 16));
                uint32_t ah[4], al[4];
                ldsm4(ah, aH + off);
                ldsm4(al, aL + off);
#pragma unroll
                for (int ni = 0; ni < 4; ++ni) {
                    const int nip = ni >> 1, q = (ni & 1) * 2;
                    mma_bf16(acc[mi][ni], ah, bh[nip][q], bh[nip][q + 1]);
                    mma_bf16(acc[mi][ni], ah, bl[nip][q], bl[nip][q + 1]);
                    mma_bf16(acc[mi][ni], al, bh[nip][q], bh[nip][q + 1]);
                }
            }
        }
        __syncthreads();
    }

    if (OM == 0) {
#pragma unroll
        for (int mi = 0; mi < 4; ++mi) {
            const int r0 = m0 + wm * 64 + mi * 16 + (lane >> 2);
#pragma unroll
            for (int ni = 0; ni < 4; ++ni) {
                const int c0 = n0 + wn * 32 + ni * 8 + (lane & 3) * 2;
                const float bv0 = bias[c0], bv1 = bias[c0 + 1];
                out0[(size_t)r0 * GK + c0]           = acc[mi][ni][0] + bv0;
                out0[(size_t)r0 * GK + c0 + 1]       = acc[mi][ni][1] + bv1;
                out0[(size_t)(r0 + 8) * GK + c0]     = acc[mi][ni][2] + bv0;
                out0[(size_t)(r0 + 8) * GK + c0 + 1] = acc[mi][ni][3] + bv1;
            }
        }
    } else {
        __half* sh = (z == 0) ? sh0 : ((z == 1) ? sh1 : sh2);
        __half* sl = (z == 0) ? sl0 : ((z == 1) ? sl1 : sl2);
        const float cs = (z == 0) ? scale0 : 1.0f;
#pragma unroll
        for (int mi = 0; mi < 4; ++mi) {
            const int r0 = m0 + wm * 64 + mi * 16 + (lane >> 2);
#pragma unroll
            for (int ni = 0; ni < 4; ++ni) {
                const int c0 = n0 + wn * 32 + ni * 8 + (lane & 3) * 2;
                const float bv0 = bias[c0], bv1 = bias[c0 + 1];
                float v00 = (acc[mi][ni][0] + bv0) * cs;
                float v01 = (acc[mi][ni][1] + bv1) * cs;
                float v10 = (acc[mi][ni][2] + bv0) * cs;
                float v11 = (acc[mi][ni][3] + bv1) * cs;
                __half2 h0 = __floats2half2_rn(v00, v01);
                __half2 h1 = __floats2half2_rn(v10, v11);
                __half2 l0 = __floats2half2_rn(v00 - __half2float(h0.x),
                                               v01 - __half2float(h0.y));
                __half2 l1 = __floats2half2_rn(v10 - __half2float(h1.x),
                                               v11 - __half2float(h1.y));
                *(__half2*)(sh + (size_t)r0 * GK + c0)       = h0;
                *(__half2*)(sl + (size_t)r0 * GK + c0)       = l0;
                *(__half2*)(sh + (size_t)(r0 + 8) * GK + c0) = h1;
                *(__half2*)(sl + (size_t)(r0 + 8) * GK + c0) = l1;
            }
        }
    }
}

// ---------------------------------------------------------------------------
// HMMA causal flash attention, fp16 split inputs, log2-domain softmax.
// CTA: 64 q-rows x 64-key tiles, 4 warps (warp w: q rows w*16..w*16+15).
// Smem: Qh(8K) Ql(8K) + 2 stages of {Kh,Kl,Vh,Vl}(32K each) = 80K.
// Output: bf16 hi/lo split of attn output (consumed by O-proj GEMM).
// ---------------------------------------------------------------------------
#define ATT_SMEM (16384 + 2 * 32768)
#define ONESH2 0x3C003C00u

__global__ __launch_bounds__(128, 2) void attn_mma(
    const __half* __restrict__ Qh_g, const __half* __restrict__ Ql_g,
    const __half* __restrict__ Kh_g, const __half* __restrict__ Kl_g,
    const __half* __restrict__ Vh_g, const __half* __restrict__ Vl_g,
    __nv_bfloat16* __restrict__ Oh_g, __nv_bfloat16* __restrict__ Ol_g)
{
    extern __shared__ char smem[];
    const uint32_t sb = smem_u32(smem);
    const int tid = threadIdx.x;
    const int lane = tid & 31, w = tid >> 5;
    const int mt = (int)gridDim.x - 1 - (int)blockIdx.x;   // heavy tiles first
    const int bh = blockIdx.z;
    const int b = bh >> 4, h = bh & 15;
    const int m0 = mt * 64;
    const int base = b * SEQ;
    const int hoff = h * HDIM;

    // loader mapping: 2 threads/row, 4 16B chunks each
    const int lr = tid >> 1;
    const int lc4 = (tid & 1) * 4;
    const uint32_t lrow128 = (uint32_t)(lr * 128);
    const int lswz = lr & 7;
    const __half* gQh = Qh_g + (size_t)(base + m0 + lr) * DMODEL + hoff + lc4 * 8;
    const __half* gQl = Ql_g + (size_t)(base + m0 + lr) * DMODEL + hoff + lc4 * 8;
    const __half* gKh = Kh_g + (size_t)(base + lr) * DMODEL + hoff + lc4 * 8;
    const __half* gKl = Kl_g + (size_t)(base + lr) * DMODEL + hoff + lc4 * 8;
    const __half* gVh = Vh_g + (size_t)(base + lr) * DMODEL + hoff + lc4 * 8;
    const __half* gVl = Vl_g + (size_t)(base + lr) * DMODEL + hoff + lc4 * 8;

    const uint32_t QH = sb, QL = sb + 8192;

    // prologue: Q tile + KV stage 0 in one group
    {
#pragma unroll
        for (int j = 0; j < 4; ++j) {
            uint32_t sw = (uint32_t)(((lc4 + j) ^ lswz) * 16);
            cp16(QH + lrow128 + sw, gQh + j * 8);
            cp16(QL + lrow128 + sw, gQl + j * 8);
            uint32_t st = sb + 16384 + lrow128 + sw;
            cp16(st,         gKh + j * 8);
            cp16(st + 8192,  gKl + j * 8);
            cp16(st + 16384, gVh + j * 8);
            cp16(st + 24576, gVl + j * 8);
        }
        asm volatile("cp.async.commit_group;");
    }

    // ldmatrix lane decode
    const int arow = (lane & 7) + ((lane >> 3) & 1) * 8;
    const int akb  = lane >> 4;
    const int bnof = ((lane >> 4) << 3) + (lane & 7);
    const int bkb  = (lane >> 3) & 1;
    const int trow_l = (lane & 7) + ((lane >> 3) & 1) * 8;   // V trans row within 16
    const int tchk_l = lane >> 4;                            // V trans d-chunk sel

    float oacc[8][4];
    float lf[4];
    float mrow[2] = { -1e30f, -1e30f };
#pragma unroll
    for (int i = 0; i < 8; ++i)
#pragma unroll
        for (int e = 0; e < 4; ++e) oacc[i][e] = 0.f;
#pragma unroll
    for (int e = 0; e < 4; ++e) lf[e] = 0.f;

    uint32_t qfh[4][4], qfl[4][4];
    bool qloaded = false;

    for (int j = 0; j <= mt; ++j) {
        if (j < mt) {
            const size_t koff = (size_t)(j + 1) * 64 * DMODEL;
            uint32_t st = sb + 16384 + ((j + 1) & 1) * 32768 + lrow128;
#pragma unroll
            for (int jj = 0; jj < 4; ++jj) {
                uint32_t sw = (uint32_t)(((lc4 + jj) ^ lswz) * 16);
                cp16(st + sw,         gKh + koff + jj * 8);
                cp16(st + 8192 + sw,  gKl + koff + jj * 8);
                cp16(st + 16384 + sw, gVh + koff + jj * 8);
                cp16(st + 24576 + sw, gVl + koff + jj * 8);
            }
            asm volatile("cp.async.commit_group;");
            asm volatile("cp.async.wait_group 1;");
        } else {
            asm volatile("cp.async.wait_group 0;");
        }
        __syncthreads();

        if (!qloaded) {   // hoist Q fragments into registers once
#pragma unroll
            for (int kk = 0; kk < 4; ++kk) {
                const int qr = w * 16 + arow;
                uint32_t off = (uint32_t)(qr * 128 + (((kk * 2 + akb) ^ (qr & 7)) * 16));
                ldsm4(qfh[kk], QH + off);
                ldsm4(qfl[kk], QL + off);
            }
            qloaded = true;
        }

        const uint32_t KH = sb + 16384 + (j & 1) * 32768;
        const uint32_t KL = KH + 8192;
        const uint32_t VH = KH + 16384;
        const uint32_t VL = KH + 24576;

        // ---- S = Qs K^T (log2-domain scores), split-3 fp16 ----
        float sacc[8][4];
#pragma unroll
        for (int i = 0; i < 8; ++i)
#pragma unroll
            for (int e = 0; e < 4; ++e) sacc[i][e] = 0.f;

#pragma unroll
        for (int kk = 0; kk < 4; ++kk) {
#pragma unroll
            for (int np = 0; np < 4; ++np) {
                const int nr = np * 16 + bnof;
                uint32_t off = (uint32_t)(nr * 128 + (((kk * 2 + bkb) ^ (nr & 7)) * 16));
                uint32_t bkh[4], bkl[4];
                ldsm4(bkh, KH + off);
                ldsm4(bkl, KL + off);
#pragma unroll
                for (int hf = 0; hf < 2; ++hf) {
                    const int ni = np * 2 + hf, q2 = hf * 2;
                    mma_f16(sacc[ni], qfh[kk], bkh[q2], bkh[q2 + 1]);
                    mma_f16(sacc[ni], qfh[kk], bkl[q2], bkl[q2 + 1]);
                    mma_f16(sacc[ni], qfl[kk], bkh[q2], bkh[q2 + 1]);
                }
            }
        }

        // ---- causal mask on diagonal tile ----
        if (j == mt) {
            const int rl0 = w * 16 + (lane >> 2);
            const int cl0 = (lane & 3) * 2;
#pragma unroll
            for (int ni = 0; ni < 8; ++ni) {
#pragma unroll
                for (int e = 0; e < 4; ++e) {
                    int col = ni * 8 + cl0 + (e & 1);
                    int row = rl0 + ((e >> 1) << 3);
                    if (col > row) sacc[ni][e] = -1e30f;
                }
            }
        }

        // ---- online softmax (log2 domain) ----
        float mnew0, mnew1;
        {
            float mx0 = -1e30f, mx1 = -1e30f;
#pragma unroll
            for (int ni = 0; ni < 8; ++ni) {
                mx0 = fmaxf(mx0, fmaxf(sacc[ni][0], sacc[ni][1]));
                mx1 = fmaxf(mx1, fmaxf(sacc[ni][2], sacc[ni][3]));
            }
            mx0 = fmaxf(mx0, __shfl_xor_sync(0xffffffffu, mx0, 1));
            mx0 = fmaxf(mx0, __shfl_xor_sync(0xffffffffu, mx0, 2));
            mx1 = fmaxf(mx1, __shfl_xor_sync(0xffffffffu, mx1, 1));
            mx1 = fmaxf(mx1, __shfl_xor_sync(0xffffffffu, mx1, 2));
            mnew0 = fmaxf(mrow[0], mx0);
            mnew1 = fmaxf(mrow[1], mx1);
            float al0 = ex2f(mrow[0] - mnew0);
            float al1 = ex2f(mrow[1] - mnew1);
            mrow[0] = mnew0; mrow[1] = mnew1;
#pragma unroll
            for (int ni = 0; ni < 8; ++ni) {
                oacc[ni][0] *= al0; oacc[ni][1] *= al0;
                oacc[ni][2] *= al1; oacc[ni][3] *= al1;
            }
            lf[0] *= al0; lf[1] *= al0; lf[2] *= al1; lf[3] *= al1;
        }

        // ---- P = 2^(s - m) as fp16 pairs (A-fragment form) ----
        uint32_t pfr[8][2];
#pragma unroll
        for (int ni = 0; ni < 8; ++ni) {
            pfr[ni][0] = exp2_f16x2(sacc[ni][0] - mnew0, sacc[ni][1] - mnew0);
            pfr[ni][1] = exp2_f16x2(sacc[ni][2] - mnew1, sacc[ni][3] - mnew1);
        }

        // ---- l += P @ ones, O += P @ (Vh + Vl) ----
#pragma unroll
        for (int t = 0; t < 4; ++t) {
            uint32_t a[4] = { pfr[2 * t][0], pfr[2 * t][1],
                              pfr[2 * t + 1][0], pfr[2 * t + 1][1] };
            mma_f16(lf, a, ONESH2, ONESH2);
#pragma unroll
            for (int dnp = 0; dnp < 4; ++dnp) {
                const int tr = t * 16 + trow_l;
                uint32_t off = (uint32_t)(tr * 128 +
                               (((dnp * 2 + tchk_l) ^ (tr & 7)) * 16));
                uint32_t vh[4], vl[4];
                ldsm4t(vh, VH + off);
                ldsm4t(vl, VL + off);
                mma_f16(oacc[dnp * 2], a, vh[0], vh[1]);
                mma_f16(oacc[dnp * 2], a, vl[0], vl[1]);
                mma_f16(oacc[dnp * 2 + 1], a, vh[2], vh[3]);
                mma_f16(oacc[dnp * 2 + 1], a, vl[2], vl[3]);
            }
        }
        __syncthreads();
    }

    // ---- normalize + bf16 split output ----
    const float inv0 = 1.f / lf[0];
    const float inv1 = 1.f / lf[2];
    const int r0g = base + m0 + w * 16 + (lane >> 2);
    const int cq = (lane & 3) * 2;
#pragma unroll
    for (int ni = 0; ni < 8; ++ni) {
        const int col = hoff + ni * 8 + cq;
        float v00 = oacc[ni][0] * inv0, v01 = oacc[ni][1] * inv0;
        float v10 = oacc[ni][2] * inv1, v11 = oacc[ni][3] * inv1;
        __nv_bfloat162 h0 = __floats2bfloat162_rn(v00, v01);
        __nv_bfloat162 h1 = __floats2bfloat162_rn(v10, v11);
        __nv_bfloat162 l0 = __floats2bfloat162_rn(v00 - __bfloat162float(h0.x),
                                                  v01 - __bfloat162float(h0.y));
        __nv_bfloat162 l1 = __floats2bfloat162_rn(v10 - __bfloat162float(h1.x),
                                                  v11 - __bfloat162float(h1.y));
        *(__nv_bfloat162*)(Oh_g + (size_t)r0g * DMODEL + col)       = h0;
        *(__nv_bfloat162*)(Ol_g + (size_t)r0g * DMODEL + col)       = l0;
        *(__nv_bfloat162*)(Oh_g + (size_t)(r0g + 8) * DMODEL + col) = h1;
        *(__nv_bfloat162*)(Ol_g + (size_t)(r0g + 8) * DMODEL + col) = l1;
    }
}

// ---------------------------------------------------------------------------
extern "C" void kernel_launch(void* const* d_in, const int* in_sizes, int n_in,
                              void* d_out, int out_size)
{
    const float* X  = (const float*)d_in[0];
    const float* Wq = (const float*)d_in[1];
    const float* bq = (const float*)d_in[2];
    const float* Wk = (const float*)d_in[3];
    const float* bk = (const float*)d_in[4];
    const float* Wv = (const float*)d_in[5];
    const float* bv = (const float*)d_in[6];
    const float* Wo = (const float*)d_in[7];
    const float* bo = (const float*)d_in[8];
    float* Y = (float*)d_out;

    __nv_bfloat16 *xh, *xl, *wh, *wl, *ah, *al;
    __half *qh, *ql, *kh, *kl, *vh, *vl;
    cudaGetSymbolAddress((void**)&xh, g_xh);
    cudaGetSymbolAddress((void**)&xl, g_xl);
    cudaGetSymbolAddress((void**)&wh, g_wh);
    cudaGetSymbolAddress((void**)&wl, g_wl);
    cudaGetSymbolAddress((void**)&ah, g_ah);
    cudaGetSymbolAddress((void**)&al, g_al);
    cudaGetSymbolAddress((void**)&qh, g_qh);
    cudaGetSymbolAddress((void**)&ql, g_ql);
    cudaGetSymbolAddress((void**)&kh, g_kh);
    cudaGetSymbolAddress((void**)&kl, g_kl);
    cudaGetSymbolAddress((void**)&vh, g_vh);
    cudaGetSymbolAddress((void**)&vl, g_vl);

    cudaFuncSetAttribute(gemm_mma<0>,
                         cudaFuncAttributeMaxDynamicSharedMemorySize, GEMM_SMEM);
    cudaFuncSetAttribute(gemm_mma<1>,
                         cudaFuncAttributeMaxDynamicSharedMemorySize, GEMM_SMEM);
    cudaFuncSetAttribute(attn_mma,
                         cudaFuncAttributeMaxDynamicSharedMemorySize, ATT_SMEM);

    const int WN4 = DMODEL * DMODEL / 4;
    split_kernel<<<MROWS * DMODEL / 4 / 256, 256>>>(X, xh, xl, MROWS * DMODEL / 4);
    split_kernel<<<WN4 / 256, 256>>>(Wq, wh + 0 * DMODEL * DMODEL, wl + 0 * DMODEL * DMODEL, WN4);
    split_kernel<<<WN4 / 256, 256>>>(Wk, wh + 1 * DMODEL * DMODEL, wl + 1 * DMODEL * DMODEL, WN4);
    split_kernel<<<WN4 / 256, 256>>>(Wv, wh + 2 * DMODEL * DMODEL, wl + 2 * DMODEL * DMODEL, WN4);
    split_kernel<<<WN4 / 256, 256>>>(Wo, wh + 3 * DMODEL * DMODEL, wl + 3 * DMODEL * DMODEL, WN4);

    // QKV projections -> fp16 hi/lo splits (Q pre-scaled into log2 domain)
    dim3 gqkv(DMODEL / 128, MROWS / 128, 3);
    gemm_mma<1><<<gqkv, 256, GEMM_SMEM>>>(xh, xl, wh, wl, bq, bk, bv,
                                          nullptr,
                                          qh, ql, kh, kl, vh, vl, QSCALE);

    // flash attention (HMMA) -> bf16 hi/lo split output
    dim3 gattn(SEQ / 64, 1, NB * NH);
    attn_mma<<<gattn, 128, ATT_SMEM>>>(qh, ql, kh, kl, vh, vl, ah, al);

    // O projection -> fp32 Y
    dim3 go(DMODEL / 128, MROWS / 128, 1);
    gemm_mma<0><<<go, 256, GEMM_SMEM>>>(ah, al, wh + 3 * DMODEL * DMODEL,
                                        wl + 3 * DMODEL * DMODEL,
                                        bo, bo, bo, Y,
                                        nullptr, nullptr, nullptr,
                                        nullptr, nullptr, nullptr, 1.0f);
}

// round 6
// speedup vs baseline: 5.8495x; 1.8879x over previous
#include <cuda_runtime.h>
#include <cuda_bf16.h>
#include <cuda_fp16.h>
#include <stdint.h>

#define SEQ    2048
#define DMODEL 1024
#define NH     16
#define HDIM   64
#define NB     2
#define MROWS  (NB * SEQ)   // 4096
#define GK     DMODEL

#define QSCALE 0.18033688011112042f   // 0.125 * log2(e)

// Scratch (device globals: no allocation allowed in kernel_launch)
__device__ __half g_xf[MROWS * DMODEL];
__device__ __half g_wf[3 * DMODEL * DMODEL];
__device__ __nv_bfloat16 g_wh[DMODEL * DMODEL];   // Wo hi
__device__ __nv_bfloat16 g_wl[DMODEL * DMODEL];   // Wo lo
__device__ __half g_qh[MROWS * DMODEL];
__device__ __half g_kh[MROWS * DMODEL];
__device__ __half g_vh[MROWS * DMODEL];
__device__ __nv_bfloat16 g_ah[MROWS * DMODEL];
__device__ __nv_bfloat16 g_al[MROWS * DMODEL];

// ---------------------------------------------------------------------------
// helpers (all baseline PTX: sm_80-class, no 'a'-suffix features)
// ---------------------------------------------------------------------------
__device__ __forceinline__ uint32_t smem_u32(const void* p) {
    uint32_t a;
    asm("{ .reg .u64 t; cvta.to.shared.u64 t, %1; cvt.u32.u64 %0, t; }"
        : "=r"(a) : "l"(p));
    return a;
}

__device__ __forceinline__ void cp16(uint32_t s, const void* g) {
    asm volatile("cp.async.cg.shared.global [%0], [%1], 16;" :: "r"(s), "l"(g));
}

__device__ __forceinline__ void ldsm4(uint32_t* r, uint32_t a) {
    asm volatile("ldmatrix.sync.aligned.m8n8.x4.shared.b16 {%0,%1,%2,%3}, [%4];"
                 : "=r"(r[0]), "=r"(r[1]), "=r"(r[2]), "=r"(r[3]) : "r"(a));
}

__device__ __forceinline__ void ldsm4t(uint32_t* r, uint32_t a) {
    asm volatile("ldmatrix.sync.aligned.m8n8.x4.trans.shared.b16 {%0,%1,%2,%3}, [%4];"
                 : "=r"(r[0]), "=r"(r[1]), "=r"(r[2]), "=r"(r[3]) : "r"(a));
}

__device__ __forceinline__ void mma_bf16(float* d, const uint32_t* a,
                                         uint32_t b0, uint32_t b1) {
    asm volatile(
        "mma.sync.aligned.m16n8k16.row.col.f32.bf16.bf16.f32 "
        "{%0,%1,%2,%3}, {%4,%5,%6,%7}, {%8,%9}, {%0,%1,%2,%3};"
        : "+f"(d[0]), "+f"(d[1]), "+f"(d[2]), "+f"(d[3])
        : "r"(a[0]), "r"(a[1]), "r"(a[2]), "r"(a[3]), "r"(b0), "r"(b1));
}

__device__ __forceinline__ void mma_f16(float* d, const uint32_t* a,
                                        uint32_t b0, uint32_t b1) {
    asm volatile(
        "mma.sync.aligned.m16n8k16.row.col.f32.f16.f16.f32 "
        "{%0,%1,%2,%3}, {%4,%5,%6,%7}, {%8,%9}, {%0,%1,%2,%3};"
        : "+f"(d[0]), "+f"(d[1]), "+f"(d[2]), "+f"(d[3])
        : "r"(a[0]), "r"(a[1]), "r"(a[2]), "r"(a[3]), "r"(b0), "r"(b1));
}

__device__ __forceinline__ float ex2f(float x) {
    float r;
    asm("ex2.approx.f32 %0, %1;" : "=f"(r) : "f"(x));
    return r;
}

// pack (lo,hi) to f16x2 then 2^x elementwise
__device__ __forceinline__ uint32_t exp2_f16x2(float lo, float hi) {
    uint32_t p, r;
    asm("cvt.rn.f16x2.f32 %0, %1, %2;" : "=r"(p) : "f"(hi), "f"(lo));
    asm("ex2.approx.f16x2 %0, %1;" : "=r"(r) : "r"(p));
    return r;
}

// ---------------------------------------------------------------------------
// fp32 -> fp16 convert, vectorized by 4
// ---------------------------------------------------------------------------
__global__ __launch_bounds__(256) void tofp16_kernel(
    const float* __restrict__ in, __half* __restrict__ out, int n4)
{
    int i = blockIdx.x * blockDim.x + threadIdx.x;
    if (i >= n4) return;
    float4 v = ((const float4*)in)[i];
    ((__half2*)out)[2 * i]     = __floats2half2_rn(v.x, v.y);
    ((__half2*)out)[2 * i + 1] = __floats2half2_rn(v.z, v.w);
}

// ---------------------------------------------------------------------------
// fp32 -> (bf16 hi, bf16 residual) split, vectorized by 4 (for Wo only)
// ---------------------------------------------------------------------------
__global__ __launch_bounds__(256) void split_kernel(
    const float* __restrict__ in, __nv_bfloat16* __restrict__ hi,
    __nv_bfloat16* __restrict__ lo, int n4)
{
    int i = blockIdx.x * blockDim.x + threadIdx.x;
    if (i >= n4) return;
    float4 v = ((const float4*)in)[i];
    __nv_bfloat162 h0 = __floats2bfloat162_rn(v.x, v.y);
    __nv_bfloat162 h1 = __floats2bfloat162_rn(v.z, v.w);
    __nv_bfloat162 l0 = __floats2bfloat162_rn(v.x - __bfloat162float(h0.x),
                                              v.y - __bfloat162float(h0.y));
    __nv_bfloat162 l1 = __floats2bfloat162_rn(v.z - __bfloat162float(h1.x),
                                              v.w - __bfloat162float(h1.y));
    ((__nv_bfloat162*)hi)[2 * i]     = h0;
    ((__nv_bfloat162*)hi)[2 * i + 1] = h1;
    ((__nv_bfloat162*)lo)[2 * i]     = l0;
    ((__nv_bfloat162*)lo)[2 * i + 1] = l1;
}

// ---------------------------------------------------------------------------
// Single-fp16 HMMA GEMM for QKV: Out[m][n] = fp16(sum_k A[m][k]*W[n][k] + b)
// CTA 128x128, BK=64, cp.async double buffer, XOR-swizzled smem.
// z selects weight set within Wb + bias + output. z==0 output scaled (Q).
// Smem/stage 32KB: A(16K) W(16K); 2 stages.
// ---------------------------------------------------------------------------
#define GEMMF_SMEM (2 * 32768)

__global__ __launch_bounds__(256, 2) void gemm_f16(
    const __half* __restrict__ A, const __half* __restrict__ Wb,
    const float* __restrict__ bias0, const float* __restrict__ bias1,
    const float* __restrict__ bias2,
    __half* __restrict__ o0, __half* __restrict__ o1, __half* __restrict__ o2,
    float scale0)
{
    extern __shared__ char smem[];
    const int tid = threadIdx.x;
    const int z = blockIdx.z;
    const __half* W = Wb + (size_t)z * GK * GK;
    const float* bias = (z == 0) ? bias0 : ((z == 1) ? bias1 : bias2);
    __half* Out       = (z == 0) ? o0    : ((z == 1) ? o1    : o2);
    const float cs = (z == 0) ? scale0 : 1.0f;
    const int m0 = blockIdx.y * 128, n0 = blockIdx.x * 128;

    const uint32_t sb = smem_u32(smem);
    const int lane = tid & 31, warp = tid >> 5;
    const int wm = warp & 1, wn = warp >> 1;   // warp tile 64x32

    const int lr = tid >> 1;
    const int lh = (tid & 1) * 4;
    const __half* gA = A + (size_t)(m0 + lr) * GK + lh * 8;
    const __half* gW = W + (size_t)(n0 + lr) * GK + lh * 8;
    const uint32_t lrow = (uint32_t)(lr * 128);
    const int lswz = lr & 7;

    const int arow = (lane & 7) + ((lane >> 3) & 1) * 8;
    const int akb  = lane >> 4;
    const int bnof = ((lane >> 4) << 3) + (lane & 7);
    const int bkb  = (lane >> 3) & 1;

    float acc[4][4][4];
#pragma unroll
    for (int i = 0; i < 4; i++)
#pragma unroll
        for (int j = 0; j < 4; j++)
#pragma unroll
            for (int t = 0; t < 4; t++) acc[i][j][t] = 0.f;

    {
        uint32_t base = sb + lrow;
#pragma unroll
        for (int j = 0; j < 4; ++j) {
            uint32_t sw = (uint32_t)(((lh + j) ^ lswz) * 16);
            cp16(base + sw,         gA + j * 8);
            cp16(base + 16384 + sw, gW + j * 8);
        }
        asm volatile("cp.async.commit_group;");
    }

    for (int c = 0; c < GK / 64; ++c) {
        if (c + 1 < GK / 64) {
            const int k0 = (c + 1) * 64;
            uint32_t base = sb + ((c + 1) & 1) * 32768 + lrow;
#pragma unroll
            for (int j = 0; j < 4; ++j) {
                uint32_t sw = (uint32_t)(((lh + j) ^ lswz) * 16);
                cp16(base + sw,         gA + k0 + j * 8);
                cp16(base + 16384 + sw, gW + k0 + j * 8);
            }
            asm volatile("cp.async.commit_group;");
            asm volatile("cp.async.wait_group 1;");
        } else {
            asm volatile("cp.async.commit_group;");
            asm volatile("cp.async.wait_group 0;");
        }
        __syncthreads();

        const uint32_t aS = sb + (c & 1) * 32768;
        const uint32_t wS = aS + 16384;

#pragma unroll
        for (int kk = 0; kk < 4; ++kk) {
            uint32_t bw[2][4];
#pragma unroll
            for (int nip = 0; nip < 2; ++nip) {
                int n = wn * 32 + nip * 16 + bnof;
                uint32_t off = (uint32_t)(n * 128 + (((kk * 2 + bkb) ^ (n & 7)) * 16));
                ldsm4(bw[nip], wS + off);
            }
#pragma unroll
            for (int mi = 0; mi < 4; ++mi) {
                int r = wm * 64 + mi * 16 + arow;
                uint32_t off = (uint32_t)(r * 128 + (((kk * 2 + akb) ^ (r & 7)) * 16));
                uint32_t af[4];
                ldsm4(af, aS + off);
#pragma unroll
                for (int ni = 0; ni < 4; ++ni) {
                    const int nip = ni >> 1, q = (ni & 1) * 2;
                    mma_f16(acc[mi][ni], af, bw[nip][q], bw[nip][q + 1]);
                }
            }
        }
        __syncthreads();
    }

    // epilogue: bias + scale + fp16 store
#pragma unroll
    for (int mi = 0; mi < 4; ++mi) {
        const int r0 = m0 + wm * 64 + mi * 16 + (lane >> 2);
#pragma unroll
        for (int ni = 0; ni < 4; ++ni) {
            const int c0 = n0 + wn * 32 + ni * 8 + (lane & 3) * 2;
            const float bv0 = bias[c0], bv1 = bias[c0 + 1];
            *(__half2*)(Out + (size_t)r0 * GK + c0) =
                __floats2half2_rn((acc[mi][ni][0] + bv0) * cs,
                                  (acc[mi][ni][1] + bv1) * cs);
            *(__half2*)(Out + (size_t)(r0 + 8) * GK + c0) =
                __floats2half2_rn((acc[mi][ni][2] + bv0) * cs,
                                  (acc[mi][ni][3] + bv1) * cs);
        }
    }
}

// ---------------------------------------------------------------------------
// bf16 split-3 HMMA GEMM (O projection): fp32 out = A@W^T + b, A as bf16 hi/lo.
// ---------------------------------------------------------------------------
#define GEMM_SMEM (2 * 65536)

__global__ __launch_bounds__(256, 1) void gemm_mma(
    const __nv_bfloat16* __restrict__ Ah, const __nv_bfloat16* __restrict__ Al,
    const __nv_bfloat16* __restrict__ Wh, const __nv_bfloat16* __restrict__ Wl,
    const float* __restrict__ bias, float* __restrict__ out0)
{
    extern __shared__ char smem[];
    const int tid = threadIdx.x;
    const int m0 = blockIdx.y * 128, n0 = blockIdx.x * 128;

    const uint32_t sb = smem_u32(smem);
    const int lane = tid & 31, warp = tid >> 5;
    const int wm = warp & 1, wn = warp >> 1;

    const int lr = tid >> 1;
    const int lh = (tid & 1) * 4;
    const __nv_bfloat16* gAh = Ah + (size_t)(m0 + lr) * GK + lh * 8;
    const __nv_bfloat16* gAl = Al + (size_t)(m0 + lr) * GK + lh * 8;
    const __nv_bfloat16* gWh = Wh + (size_t)(n0 + lr) * GK + lh * 8;
    const __nv_bfloat16* gWl = Wl + (size_t)(n0 + lr) * GK + lh * 8;
    const uint32_t lrow = (uint32_t)(lr * 128);
    const int lswz = lr & 7;

    const int arow = (lane & 7) + ((lane >> 3) & 1) * 8;
    const int akb  = lane >> 4;
    const int bnof = ((lane >> 4) << 3) + (lane & 7);
    const int bkb  = (lane >> 3) & 1;

    float acc[4][4][4];
#pragma unroll
    for (int i = 0; i < 4; i++)
#pragma unroll
        for (int j = 0; j < 4; j++)
#pragma unroll
            for (int t = 0; t < 4; t++) acc[i][j][t] = 0.f;

    {
        uint32_t base = sb + lrow;
#pragma unroll
        for (int j = 0; j < 4; ++j) {
            uint32_t sw = (uint32_t)(((lh + j) ^ lswz) * 16);
            cp16(base + sw,         gAh + j * 8);
            cp16(base + 16384 + sw, gAl + j * 8);
            cp16(base + 32768 + sw, gWh + j * 8);
            cp16(base + 49152 + sw, gWl + j * 8);
        }
        asm volatile("cp.async.commit_group;");
    }

    for (int c = 0; c < GK / 64; ++c) {
        if (c + 1 < GK / 64) {
            const int k0 = (c + 1) * 64;
            uint32_t base = sb + ((c + 1) & 1) * 65536 + lrow;
#pragma unroll
            for (int j = 0; j < 4; ++j) {
                uint32_t sw = (uint32_t)(((lh + j) ^ lswz) * 16);
                cp16(base + sw,         gAh + k0 + j * 8);
                cp16(base + 16384 + sw, gAl + k0 + j * 8);
                cp16(base + 32768 + sw, gWh + k0 + j * 8);
                cp16(base + 49152 + sw, gWl + k0 + j * 8);
            }
            asm volatile("cp.async.commit_group;");
            asm volatile("cp.async.wait_group 1;");
        } else {
            asm volatile("cp.async.commit_group;");
            asm volatile("cp.async.wait_group 0;");
        }
        __syncthreads();

        const uint32_t aH = sb + (c & 1) * 65536;
        const uint32_t aL = aH + 16384;
        const uint32_t wH = aH + 32768;
        const uint32_t wL = aH + 49152;

#pragma unroll
        for (int kk = 0; kk < 4; ++kk) {
            uint32_t bh[2][4], bl[2][4];
#pragma unroll
            for (int nip = 0; nip < 2; ++nip) {
                int n = wn * 32 + nip * 16 + bnof;
                uint32_t off = (uint32_t)(n * 128 + (((kk * 2 + bkb) ^ (n & 7)) * 16));
                ldsm4(bh[nip], wH + off);
                ldsm4(bl[nip], wL + off);
            }
#pragma unroll
            for (int mi = 0; mi < 4; ++mi) {
                int r = wm * 64 + mi * 16 + arow;
                uint32_t off = (uint32_t)(r * 128 + (((kk * 2 + akb) ^ (r & 7)) * 16));
                uint32_t ah[4], al[4];
                ldsm4(ah, aH + off);
                ldsm4(al, aL + off);
#pragma unroll
                for (int ni = 0; ni < 4; ++ni) {
                    const int nip = ni >> 1, q = (ni & 1) * 2;
                    mma_bf16(acc[mi][ni], ah, bh[nip][q], bh[nip][q + 1]);
                    mma_bf16(acc[mi][ni], ah, bl[nip][q], bl[nip][q + 1]);
                    mma_bf16(acc[mi][ni], al, bh[nip][q], bh[nip][q + 1]);
                }
            }
        }
        __syncthreads();
    }

#pragma unroll
    for (int mi = 0; mi < 4; ++mi) {
        const int r0 = m0 + wm * 64 + mi * 16 + (lane >> 2);
#pragma unroll
        for (int ni = 0; ni < 4; ++ni) {
            const int c0 = n0 + wn * 32 + ni * 8 + (lane & 3) * 2;
            const float bv0 = bias[c0], bv1 = bias[c0 + 1];
            out0[(size_t)r0 * GK + c0]           = acc[mi][ni][0] + bv0;
            out0[(size_t)r0 * GK + c0 + 1]       = acc[mi][ni][1] + bv1;
            out0[(size_t)(r0 + 8) * GK + c0]     = acc[mi][ni][2] + bv0;
            out0[(size_t)(r0 + 8) * GK + c0 + 1] = acc[mi][ni][3] + bv1;
        }
    }
}

// ---------------------------------------------------------------------------
// HMMA causal flash attention, single-fp16 operands, log2-domain softmax.
// CTA: 64 q-rows x 64-key tiles, 4 warps. Smem: Q(8K) + 2x{K(8K),V(8K)} = 40K.
// Output: bf16 hi/lo split (consumed by O-proj split-3 GEMM).
// ---------------------------------------------------------------------------
#define ATT_SMEM (8192 + 2 * 16384)
#define ONESH2 0x3C003C00u

__global__ __launch_bounds__(128, 3) void attn_mma(
    const __half* __restrict__ Qg, const __half* __restrict__ Kg,
    const __half* __restrict__ Vg,
    __nv_bfloat16* __restrict__ Oh_g, __nv_bfloat16* __restrict__ Ol_g)
{
    extern __shared__ char smem[];
    const uint32_t sb = smem_u32(smem);
    const int tid = threadIdx.x;
    const int lane = tid & 31, w = tid >> 5;
    const int mt = (int)gridDim.x - 1 - (int)blockIdx.x;   // heavy tiles first
    const int bh = blockIdx.z;
    const int b = bh >> 4, h = bh & 15;
    const int m0 = mt * 64;
    const int base = b * SEQ;
    const int hoff = h * HDIM;

    const int lr = tid >> 1;
    const int lc4 = (tid & 1) * 4;
    const uint32_t lrow128 = (uint32_t)(lr * 128);
    const int lswz = lr & 7;
    const __half* gQ = Qg + (size_t)(base + m0 + lr) * DMODEL + hoff + lc4 * 8;
    const __half* gK = Kg + (size_t)(base + lr) * DMODEL + hoff + lc4 * 8;
    const __half* gV = Vg + (size_t)(base + lr) * DMODEL + hoff + lc4 * 8;

    const uint32_t QS = sb;

    // prologue: Q tile + KV stage 0
    {
#pragma unroll
        for (int j = 0; j < 4; ++j) {
            uint32_t sw = (uint32_t)(((lc4 + j) ^ lswz) * 16);
            cp16(QS + lrow128 + sw, gQ + j * 8);
            uint32_t st = sb + 8192 + lrow128 + sw;
            cp16(st,        gK + j * 8);
            cp16(st + 8192, gV + j * 8);
        }
        asm volatile("cp.async.commit_group;");
    }

    const int arow = (lane & 7) + ((lane >> 3) & 1) * 8;
    const int akb  = lane >> 4;
    const int bnof = ((lane >> 4) << 3) + (lane & 7);
    const int bkb  = (lane >> 3) & 1;
    const int trow_l = (lane & 7) + ((lane >> 3) & 1) * 8;
    const int tchk_l = lane >> 4;

    float oacc[8][4];
    float lf[4];
    float mrow[2] = { -1e30f, -1e30f };
#pragma unroll
    for (int i = 0; i < 8; ++i)
#pragma unroll
        for (int e = 0; e < 4; ++e) oacc[i][e] = 0.f;
#pragma unroll
    for (int e = 0; e < 4; ++e) lf[e] = 0.f;

    uint32_t qf[4][4];
    bool qloaded = false;

    for (int j = 0; j <= mt; ++j) {
        if (j < mt) {
            const size_t koff = (size_t)(j + 1) * 64 * DMODEL;
            uint32_t st = sb + 8192 + ((j + 1) & 1) * 16384 + lrow128;
#pragma unroll
            for (int jj = 0; jj < 4; ++jj) {
                uint32_t sw = (uint32_t)(((lc4 + jj) ^ lswz) * 16);
                cp16(st + sw,        gK + koff + jj * 8);
                cp16(st + 8192 + sw, gV + koff + jj * 8);
            }
            asm volatile("cp.async.commit_group;");
            asm volatile("cp.async.wait_group 1;");
        } else {
            asm volatile("cp.async.wait_group 0;");
        }
        __syncthreads();

        if (!qloaded) {
#pragma unroll
            for (int kk = 0; kk < 4; ++kk) {
                const int qr = w * 16 + arow;
                uint32_t off = (uint32_t)(qr * 128 + (((kk * 2 + akb) ^ (qr & 7)) * 16));
                ldsm4(qf[kk], QS + off);
            }
            qloaded = true;
        }

        const uint32_t KS = sb + 8192 + (j & 1) * 16384;
        const uint32_t VS = KS + 8192;

        // ---- S = Q K^T (log2-domain scores) ----
        float sacc[8][4];
#pragma unroll
        for (int i = 0; i < 8; ++i)
#pragma unroll
            for (int e = 0; e < 4; ++e) sacc[i][e] = 0.f;

#pragma unroll
        for (int kk = 0; kk < 4; ++kk) {
#pragma unroll
            for (int np = 0; np < 4; ++np) {
                const int nr = np * 16 + bnof;
                uint32_t off = (uint32_t)(nr * 128 + (((kk * 2 + bkb) ^ (nr & 7)) * 16));
                uint32_t bk[4];
                ldsm4(bk, KS + off);
                mma_f16(sacc[np * 2],     qf[kk], bk[0], bk[1]);
                mma_f16(sacc[np * 2 + 1], qf[kk], bk[2], bk[3]);
            }
        }

        // ---- causal mask on diagonal tile ----
        if (j == mt) {
            const int rl0 = w * 16 + (lane >> 2);
            const int cl0 = (lane & 3) * 2;
#pragma unroll
            for (int ni = 0; ni < 8; ++ni) {
#pragma unroll
                for (int e = 0; e < 4; ++e) {
                    int col = ni * 8 + cl0 + (e & 1);
                    int row = rl0 + ((e >> 1) << 3);
                    if (col > row) sacc[ni][e] = -1e30f;
                }
            }
        }

        // ---- online softmax (log2 domain) ----
        float mnew0, mnew1;
        {
            float mx0 = -1e30f, mx1 = -1e30f;
#pragma unroll
            for (int ni = 0; ni < 8; ++ni) {
                mx0 = fmaxf(mx0, fmaxf(sacc[ni][0], sacc[ni][1]));
                mx1 = fmaxf(mx1, fmaxf(sacc[ni][2], sacc[ni][3]));
            }
            mx0 = fmaxf(mx0, __shfl_xor_sync(0xffffffffu, mx0, 1));
            mx0 = fmaxf(mx0, __shfl_xor_sync(0xffffffffu, mx0, 2));
            mx1 = fmaxf(mx1, __shfl_xor_sync(0xffffffffu, mx1, 1));
            mx1 = fmaxf(mx1, __shfl_xor_sync(0xffffffffu, mx1, 2));
            mnew0 = fmaxf(mrow[0], mx0);
            mnew1 = fmaxf(mrow[1], mx1);
            float al0 = ex2f(mrow[0] - mnew0);
            float al1 = ex2f(mrow[1] - mnew1);
            mrow[0] = mnew0; mrow[1] = mnew1;
#pragma unroll
            for (int ni = 0; ni < 8; ++ni) {
                oacc[ni][0] *= al0; oacc[ni][1] *= al0;
                oacc[ni][2] *= al1; oacc[ni][3] *= al1;
            }
            lf[0] *= al0; lf[1] *= al0; lf[2] *= al1; lf[3] *= al1;
        }

        // ---- P = 2^(s - m) as fp16 pairs ----
        uint32_t pfr[8][2];
#pragma unroll
        for (int ni = 0; ni < 8; ++ni) {
            pfr[ni][0] = exp2_f16x2(sacc[ni][0] - mnew0, sacc[ni][1] - mnew0);
            pfr[ni][1] = exp2_f16x2(sacc[ni][2] - mnew1, sacc[ni][3] - mnew1);
        }

        // ---- l += P @ ones, O += P @ V ----
#pragma unroll
        for (int t = 0; t < 4; ++t) {
            uint32_t a[4] = { pfr[2 * t][0], pfr[2 * t][1],
                              pfr[2 * t + 1][0], pfr[2 * t + 1][1] };
            mma_f16(lf, a, ONESH2, ONESH2);
#pragma unroll
            for (int dnp = 0; dnp < 4; ++dnp) {
                const int tr = t * 16 + trow_l;
                uint32_t off = (uint32_t)(tr * 128 +
                               (((dnp * 2 + tchk_l) ^ (tr & 7)) * 16));
                uint32_t vv[4];
                ldsm4t(vv, VS + off);
                mma_f16(oacc[dnp * 2],     a, vv[0], vv[1]);
                mma_f16(oacc[dnp * 2 + 1], a, vv[2], vv[3]);
            }
        }
        __syncthreads();
    }

    // ---- normalize + bf16 split output ----
    const float inv0 = 1.f / lf[0];
    const float inv1 = 1.f / lf[2];
    const int r0g = base + m0 + w * 16 + (lane >> 2);
    const int cq = (lane & 3) * 2;
#pragma unroll
    for (int ni = 0; ni < 8; ++ni) {
        const int col = hoff + ni * 8 + cq;
        float v00 = oacc[ni][0] * inv0, v01 = oacc[ni][1] * inv0;
        float v10 = oacc[ni][2] * inv1, v11 = oacc[ni][3] * inv1;
        __nv_bfloat162 h0 = __floats2bfloat162_rn(v00, v01);
        __nv_bfloat162 h1 = __floats2bfloat162_rn(v10, v11);
        __nv_bfloat162 l0 = __floats2bfloat162_rn(v00 - __bfloat162float(h0.x),
                                                  v01 - __bfloat162float(h0.y));
        __nv_bfloat162 l1 = __floats2bfloat162_rn(v10 - __bfloat162float(h1.x),
                                                  v11 - __bfloat162float(h1.y));
        *(__nv_bfloat162*)(Oh_g + (size_t)r0g * DMODEL + col)       = h0;
        *(__nv_bfloat162*)(Ol_g + (size_t)r0g * DMODEL + col)       = l0;
        *(__nv_bfloat162*)(Oh_g + (size_t)(r0g + 8) * DMODEL + col) = h1;
        *(__nv_bfloat162*)(Ol_g + (size_t)(r0g + 8) * DMODEL + col) = l1;
    }
}

// ---------------------------------------------------------------------------
extern "C" void kernel_launch(void* const* d_in, const int* in_sizes, int n_in,
                              void* d_out, int out_size)
{
    const float* X  = (const float*)d_in[0];
    const float* Wq = (const float*)d_in[1];
    const float* bq = (const float*)d_in[2];
    const float* Wk = (const float*)d_in[3];
    const float* bk = (const float*)d_in[4];
    const float* Wv = (const float*)d_in[5];
    const float* bv = (const float*)d_in[6];
    const float* Wo = (const float*)d_in[7];
    const float* bo = (const float*)d_in[8];
    float* Y = (float*)d_out;

    __half *xf, *wf, *qh, *kh, *vh;
    __nv_bfloat16 *wh, *wl, *ah, *al;
    cudaGetSymbolAddress((void**)&xf, g_xf);
    cudaGetSymbolAddress((void**)&wf, g_wf);
    cudaGetSymbolAddress((void**)&wh, g_wh);
    cudaGetSymbolAddress((void**)&wl, g_wl);
    cudaGetSymbolAddress((void**)&qh, g_qh);
    cudaGetSymbolAddress((void**)&kh, g_kh);
    cudaGetSymbolAddress((void**)&vh, g_vh);
    cudaGetSymbolAddress((void**)&ah, g_ah);
    cudaGetSymbolAddress((void**)&al, g_al);

    cudaFuncSetAttribute(gemm_f16,
                         cudaFuncAttributeMaxDynamicSharedMemorySize, GEMMF_SMEM);
    cudaFuncSetAttribute(gemm_mma,
                         cudaFuncAttributeMaxDynamicSharedMemorySize, GEMM_SMEM);
    cudaFuncSetAttribute(attn_mma,
                         cudaFuncAttributeMaxDynamicSharedMemorySize, ATT_SMEM);

    const int XN4 = MROWS * DMODEL / 4;
    const int WN4 = DMODEL * DMODEL / 4;
    tofp16_kernel<<<XN4 / 256, 256>>>(X, xf, XN4);
    tofp16_kernel<<<WN4 / 256, 256>>>(Wq, wf + 0 * DMODEL * DMODEL, WN4);
    tofp16_kernel<<<WN4 / 256, 256>>>(Wk, wf + 1 * DMODEL * DMODEL, WN4);
    tofp16_kernel<<<WN4 / 256, 256>>>(Wv, wf + 2 * DMODEL * DMODEL, WN4);
    split_kernel<<<WN4 / 256, 256>>>(Wo, wh, wl, WN4);

    // QKV projections -> fp16 (Q pre-scaled into log2 domain)
    dim3 gqkv(DMODEL / 128, MROWS / 128, 3);
    gemm_f16<<<gqkv, 256, GEMMF_SMEM>>>(xf, wf, bq, bk, bv,
                                        qh, kh, vh, QSCALE);

    // flash attention (HMMA) -> bf16 hi/lo split output
    dim3 gattn(SEQ / 64, 1, NB * NH);
    attn_mma<<<gattn, 128, ATT_SMEM>>>(qh, kh, vh, ah, al);

    // O projection (bf16 split-3, exact) -> fp32 Y
    dim3 go(DMODEL / 128, MROWS / 128, 1);
    gemm_mma<<<go, 256, GEMM_SMEM>>>(ah, al, wh, wl, bo, Y);
}

// round 7
// speedup vs baseline: 7.3386x; 1.2546x over previous
#include <cuda_runtime.h>
#include <cuda_fp16.h>
#include <stdint.h>

#define SEQ    2048
#define DMODEL 1024
#define NH     16
#define HDIM   64
#define NB     2
#define MROWS  (NB * SEQ)   // 4096
#define GK     DMODEL

#define QSCALE 0.18033688011112042f   // 0.125 * log2(e)

// Scratch (device globals: no allocation allowed in kernel_launch)
__device__ __half g_xf[MROWS * DMODEL];
__device__ __half g_wf[4 * DMODEL * DMODEL];   // Wq, Wk, Wv, Wo (fp16)
__device__ __half g_qh[MROWS * DMODEL];
__device__ __half g_kh[MROWS * DMODEL];
__device__ __half g_vh[MROWS * DMODEL];
__device__ __half g_af[MROWS * DMODEL];        // attention output (fp16)

// ---------------------------------------------------------------------------
// helpers (all baseline PTX: sm_80-class, no 'a'-suffix features)
// ---------------------------------------------------------------------------
__device__ __forceinline__ uint32_t smem_u32(const void* p) {
    uint32_t a;
    asm("{ .reg .u64 t; cvta.to.shared.u64 t, %1; cvt.u32.u64 %0, t; }"
        : "=r"(a) : "l"(p));
    return a;
}

__device__ __forceinline__ void cp16(uint32_t s, const void* g) {
    asm volatile("cp.async.cg.shared.global [%0], [%1], 16;" :: "r"(s), "l"(g));
}

__device__ __forceinline__ void ldsm4(uint32_t* r, uint32_t a) {
    asm volatile("ldmatrix.sync.aligned.m8n8.x4.shared.b16 {%0,%1,%2,%3}, [%4];"
                 : "=r"(r[0]), "=r"(r[1]), "=r"(r[2]), "=r"(r[3]) : "r"(a));
}

__device__ __forceinline__ void ldsm4t(uint32_t* r, uint32_t a) {
    asm volatile("ldmatrix.sync.aligned.m8n8.x4.trans.shared.b16 {%0,%1,%2,%3}, [%4];"
                 : "=r"(r[0]), "=r"(r[1]), "=r"(r[2]), "=r"(r[3]) : "r"(a));
}

__device__ __forceinline__ void mma_f16(float* d, const uint32_t* a,
                                        uint32_t b0, uint32_t b1) {
    asm volatile(
        "mma.sync.aligned.m16n8k16.row.col.f32.f16.f16.f32 "
        "{%0,%1,%2,%3}, {%4,%5,%6,%7}, {%8,%9}, {%0,%1,%2,%3};"
        : "+f"(d[0]), "+f"(d[1]), "+f"(d[2]), "+f"(d[3])
        : "r"(a[0]), "r"(a[1]), "r"(a[2]), "r"(a[3]), "r"(b0), "r"(b1));
}

__device__ __forceinline__ float ex2f(float x) {
    float r;
    asm("ex2.approx.f32 %0, %1;" : "=f"(r) : "f"(x));
    return r;
}

// pack (lo,hi) to f16x2 then 2^x elementwise
__device__ __forceinline__ uint32_t exp2_f16x2(float lo, float hi) {
    uint32_t p, r;
    asm("cvt.rn.f16x2.f32 %0, %1, %2;" : "=r"(p) : "f"(hi), "f"(lo));
    asm("ex2.approx.f16x2 %0, %1;" : "=r"(r) : "r"(p));
    return r;
}

// ---------------------------------------------------------------------------
// fp32 -> fp16 convert, vectorized by 4
// ---------------------------------------------------------------------------
__global__ __launch_bounds__(256) void tofp16_kernel(
    const float* __restrict__ in, __half* __restrict__ out, int n4)
{
    int i = blockIdx.x * blockDim.x + threadIdx.x;
    if (i >= n4) return;
    float4 v = ((const float4*)in)[i];
    ((__half2*)out)[2 * i]     = __floats2half2_rn(v.x, v.y);
    ((__half2*)out)[2 * i + 1] = __floats2half2_rn(v.z, v.w);
}

// 4 weight matrices in one launch (blockIdx.y selects)
__global__ __launch_bounds__(256) void wconv4_kernel(
    const float* __restrict__ w0, const float* __restrict__ w1,
    const float* __restrict__ w2, const float* __restrict__ w3,
    __half* __restrict__ out, int n4)
{
    int i = blockIdx.x * blockDim.x + threadIdx.x;
    if (i >= n4) return;
    const int z = blockIdx.y;
    const float* in = (z == 0) ? w0 : ((z == 1) ? w1 : ((z == 2) ? w2 : w3));
    __half* o = out + (size_t)z * DMODEL * DMODEL;
    float4 v = ((const float4*)in)[i];
    ((__half2*)o)[2 * i]     = __floats2half2_rn(v.x, v.y);
    ((__half2*)o)[2 * i + 1] = __floats2half2_rn(v.z, v.w);
}

// ---------------------------------------------------------------------------
// Single-fp16 HMMA GEMM: Out[m][n] = sum_k A[m][k]*W[n][k] + bias[n]
// CTA 128x128, BK=64, cp.async double buffer, XOR-swizzled smem.
// OM==1: 3 weight sets (z selects), fp16 out, z==0 scaled.  OM==0: fp32 out.
// Smem/stage 32KB: A(16K) W(16K); 2 stages.
// ---------------------------------------------------------------------------
#define GEMMF_SMEM (2 * 32768)

template<int OM>
__global__ __launch_bounds__(256, 2) void gemm_f16(
    const __half* __restrict__ A, const __half* __restrict__ Wb,
    const float* __restrict__ bias0, const float* __restrict__ bias1,
    const float* __restrict__ bias2,
    __half* __restrict__ o0, __half* __restrict__ o1, __half* __restrict__ o2,
    float* __restrict__ fo, float scale0)
{
    extern __shared__ char smem[];
    const int tid = threadIdx.x;
    const int z = (OM == 1) ? blockIdx.z : 0;
    const __half* W = Wb + (size_t)z * GK * GK;
    const float* bias = (z == 0) ? bias0 : ((z == 1) ? bias1 : bias2);
    const int m0 = blockIdx.y * 128, n0 = blockIdx.x * 128;

    const uint32_t sb = smem_u32(smem);
    const int lane = tid & 31, warp = tid >> 5;
    const int wm = warp & 1, wn = warp >> 1;   // warp tile 64x32

    const int lr = tid >> 1;
    const int lh = (tid & 1) * 4;
    const __half* gA = A + (size_t)(m0 + lr) * GK + lh * 8;
    const __half* gW = W + (size_t)(n0 + lr) * GK + lh * 8;
    const uint32_t lrow = (uint32_t)(lr * 128);
    const int lswz = lr & 7;

    const int arow = (lane & 7) + ((lane >> 3) & 1) * 8;
    const int akb  = lane >> 4;
    const int bnof = ((lane >> 4) << 3) + (lane & 7);
    const int bkb  = (lane >> 3) & 1;

    float acc[4][4][4];
#pragma unroll
    for (int i = 0; i < 4; i++)
#pragma unroll
        for (int j = 0; j < 4; j++)
#pragma unroll
            for (int t = 0; t < 4; t++) acc[i][j][t] = 0.f;

    {
        uint32_t base = sb + lrow;
#pragma unroll
        for (int j = 0; j < 4; ++j) {
            uint32_t sw = (uint32_t)(((lh + j) ^ lswz) * 16);
            cp16(base + sw,         gA + j * 8);
            cp16(base + 16384 + sw, gW + j * 8);
        }
        asm volatile("cp.async.commit_group;");
    }

    for (int c = 0; c < GK / 64; ++c) {
        if (c + 1 < GK / 64) {
            const int k0 = (c + 1) * 64;
            uint32_t base = sb + ((c + 1) & 1) * 32768 + lrow;
#pragma unroll
            for (int j = 0; j < 4; ++j) {
                uint32_t sw = (uint32_t)(((lh + j) ^ lswz) * 16);
                cp16(base + sw,         gA + k0 + j * 8);
                cp16(base + 16384 + sw, gW + k0 + j * 8);
            }
            asm volatile("cp.async.commit_group;");
            asm volatile("cp.async.wait_group 1;");
        } else {
            asm volatile("cp.async.commit_group;");
            asm volatile("cp.async.wait_group 0;");
        }
        __syncthreads();

        const uint32_t aS = sb + (c & 1) * 32768;
        const uint32_t wS = aS + 16384;

#pragma unroll
        for (int kk = 0; kk < 4; ++kk) {
            uint32_t bw[2][4];
#pragma unroll
            for (int nip = 0; nip < 2; ++nip) {
                int n = wn * 32 + nip * 16 + bnof;
                uint32_t off = (uint32_t)(n * 128 + (((kk * 2 + bkb) ^ (n & 7)) * 16));
                ldsm4(bw[nip], wS + off);
            }
#pragma unroll
            for (int mi = 0; mi < 4; ++mi) {
                int r = wm * 64 + mi * 16 + arow;
                uint32_t off = (uint32_t)(r * 128 + (((kk * 2 + akb) ^ (r & 7)) * 16));
                uint32_t af[4];
                ldsm4(af, aS + off);
#pragma unroll
                for (int ni = 0; ni < 4; ++ni) {
                    const int nip = ni >> 1, q = (ni & 1) * 2;
                    mma_f16(acc[mi][ni], af, bw[nip][q], bw[nip][q + 1]);
                }
            }
        }
        __syncthreads();
    }

    if (OM == 1) {
        __half* Out = (z == 0) ? o0 : ((z == 1) ? o1 : o2);
        const float cs = (z == 0) ? scale0 : 1.0f;
#pragma unroll
        for (int mi = 0; mi < 4; ++mi) {
            const int r0 = m0 + wm * 64 + mi * 16 + (lane >> 2);
#pragma unroll
            for (int ni = 0; ni < 4; ++ni) {
                const int c0 = n0 + wn * 32 + ni * 8 + (lane & 3) * 2;
                const float bv0 = bias[c0], bv1 = bias[c0 + 1];
                *(__half2*)(Out + (size_t)r0 * GK + c0) =
                    __floats2half2_rn((acc[mi][ni][0] + bv0) * cs,
                                      (acc[mi][ni][1] + bv1) * cs);
                *(__half2*)(Out + (size_t)(r0 + 8) * GK + c0) =
                    __floats2half2_rn((acc[mi][ni][2] + bv0) * cs,
                                      (acc[mi][ni][3] + bv1) * cs);
            }
        }
    } else {
#pragma unroll
        for (int mi = 0; mi < 4; ++mi) {
            const int r0 = m0 + wm * 64 + mi * 16 + (lane >> 2);
#pragma unroll
            for (int ni = 0; ni < 4; ++ni) {
                const int c0 = n0 + wn * 32 + ni * 8 + (lane & 3) * 2;
                const float bv0 = bias[c0], bv1 = bias[c0 + 1];
                fo[(size_t)r0 * GK + c0]           = acc[mi][ni][0] + bv0;
                fo[(size_t)r0 * GK + c0 + 1]       = acc[mi][ni][1] + bv1;
                fo[(size_t)(r0 + 8) * GK + c0]     = acc[mi][ni][2] + bv0;
                fo[(size_t)(r0 + 8) * GK + c0 + 1] = acc[mi][ni][3] + bv1;
            }
        }
    }
}

// ---------------------------------------------------------------------------
// HMMA causal flash attention, single-fp16 operands, log2-domain softmax.
// CTA: 64 q-rows x 64-key tiles, 4 warps. Smem: Q(8K) + 2x{K(8K),V(8K)} = 40K.
// Output: fp16 (consumed by O-proj fp16 GEMM).
// ---------------------------------------------------------------------------
#define ATT_SMEM (8192 + 2 * 16384)
#define ONESH2 0x3C003C00u

__global__ __launch_bounds__(128, 3) void attn_mma(
    const __half* __restrict__ Qg, const __half* __restrict__ Kg,
    const __half* __restrict__ Vg, __half* __restrict__ Og)
{
    extern __shared__ char smem[];
    const uint32_t sb = smem_u32(smem);
    const int tid = threadIdx.x;
    const int lane = tid & 31, w = tid >> 5;
    const int mt = (int)gridDim.x - 1 - (int)blockIdx.x;   // heavy tiles first
    const int bh = blockIdx.z;
    const int b = bh >> 4, h = bh & 15;
    const int m0 = mt * 64;
    const int base = b * SEQ;
    const int hoff = h * HDIM;

    const int lr = tid >> 1;
    const int lc4 = (tid & 1) * 4;
    const uint32_t lrow128 = (uint32_t)(lr * 128);
    const int lswz = lr & 7;
    const __half* gQ = Qg + (size_t)(base + m0 + lr) * DMODEL + hoff + lc4 * 8;
    const __half* gK = Kg + (size_t)(base + lr) * DMODEL + hoff + lc4 * 8;
    const __half* gV = Vg + (size_t)(base + lr) * DMODEL + hoff + lc4 * 8;

    const uint32_t QS = sb;

    // prologue: Q tile + KV stage 0
    {
#pragma unroll
        for (int j = 0; j < 4; ++j) {
            uint32_t sw = (uint32_t)(((lc4 + j) ^ lswz) * 16);
            cp16(QS + lrow128 + sw, gQ + j * 8);
            uint32_t st = sb + 8192 + lrow128 + sw;
            cp16(st,        gK + j * 8);
            cp16(st + 8192, gV + j * 8);
        }
        asm volatile("cp.async.commit_group;");
    }

    const int arow = (lane & 7) + ((lane >> 3) & 1) * 8;
    const int akb  = lane >> 4;
    const int bnof = ((lane >> 4) << 3) + (lane & 7);
    const int bkb  = (lane >> 3) & 1;
    const int trow_l = (lane & 7) + ((lane >> 3) & 1) * 8;
    const int tchk_l = lane >> 4;

    float oacc[8][4];
    float lf[4];
    float mrow[2] = { -1e30f, -1e30f };
#pragma unroll
    for (int i = 0; i < 8; ++i)
#pragma unroll
        for (int e = 0; e < 4; ++e) oacc[i][e] = 0.f;
#pragma unroll
    for (int e = 0; e < 4; ++e) lf[e] = 0.f;

    uint32_t qf[4][4];
    bool qloaded = false;

    for (int j = 0; j <= mt; ++j) {
        if (j < mt) {
            const size_t koff = (size_t)(j + 1) * 64 * DMODEL;
            uint32_t st = sb + 8192 + ((j + 1) & 1) * 16384 + lrow128;
#pragma unroll
            for (int jj = 0; jj < 4; ++jj) {
                uint32_t sw = (uint32_t)(((lc4 + jj) ^ lswz) * 16);
                cp16(st + sw,        gK + koff + jj * 8);
                cp16(st + 8192 + sw, gV + koff + jj * 8);
            }
            asm volatile("cp.async.commit_group;");
            asm volatile("cp.async.wait_group 1;");
        } else {
            asm volatile("cp.async.wait_group 0;");
        }
        __syncthreads();

        if (!qloaded) {
#pragma unroll
            for (int kk = 0; kk < 4; ++kk) {
                const int qr = w * 16 + arow;
                uint32_t off = (uint32_t)(qr * 128 + (((kk * 2 + akb) ^ (qr & 7)) * 16));
                ldsm4(qf[kk], QS + off);
            }
            qloaded = true;
        }

        const uint32_t KS = sb + 8192 + (j & 1) * 16384;
        const uint32_t VS = KS + 8192;

        // ---- S = Q K^T (log2-domain scores) ----
        float sacc[8][4];
#pragma unroll
        for (int i = 0; i < 8; ++i)
#pragma unroll
            for (int e = 0; e < 4; ++e) sacc[i][e] = 0.f;

#pragma unroll
        for (int kk = 0; kk < 4; ++kk) {
#pragma unroll
            for (int np = 0; np < 4; ++np) {
                const int nr = np * 16 + bnof;
                uint32_t off = (uint32_t)(nr * 128 + (((kk * 2 + bkb) ^ (nr & 7)) * 16));
                uint32_t bk[4];
                ldsm4(bk, KS + off);
                mma_f16(sacc[np * 2],     qf[kk], bk[0], bk[1]);
                mma_f16(sacc[np * 2 + 1], qf[kk], bk[2], bk[3]);
            }
        }

        // ---- causal mask on diagonal tile ----
        if (j == mt) {
            const int rl0 = w * 16 + (lane >> 2);
            const int cl0 = (lane & 3) * 2;
#pragma unroll
            for (int ni = 0; ni < 8; ++ni) {
#pragma unroll
                for (int e = 0; e < 4; ++e) {
                    int col = ni * 8 + cl0 + (e & 1);
                    int row = rl0 + ((e >> 1) << 3);
                    if (col > row) sacc[ni][e] = -1e30f;
                }
            }
        }

        // ---- online softmax (log2 domain) ----
        float mnew0, mnew1;
        {
            float mx0 = -1e30f, mx1 = -1e30f;
#pragma unroll
            for (int ni = 0; ni < 8; ++ni) {
                mx0 = fmaxf(mx0, fmaxf(sacc[ni][0], sacc[ni][1]));
                mx1 = fmaxf(mx1, fmaxf(sacc[ni][2], sacc[ni][3]));
            }
            mx0 = fmaxf(mx0, __shfl_xor_sync(0xffffffffu, mx0, 1));
            mx0 = fmaxf(mx0, __shfl_xor_sync(0xffffffffu, mx0, 2));
            mx1 = fmaxf(mx1, __shfl_xor_sync(0xffffffffu, mx1, 1));
            mx1 = fmaxf(mx1, __shfl_xor_sync(0xffffffffu, mx1, 2));
            mnew0 = fmaxf(mrow[0], mx0);
            mnew1 = fmaxf(mrow[1], mx1);
            float al0 = ex2f(mrow[0] - mnew0);
            float al1 = ex2f(mrow[1] - mnew1);
            mrow[0] = mnew0; mrow[1] = mnew1;
#pragma unroll
            for (int ni = 0; ni < 8; ++ni) {
                oacc[ni][0] *= al0; oacc[ni][1] *= al0;
                oacc[ni][2] *= al1; oacc[ni][3] *= al1;
            }
            lf[0] *= al0; lf[1] *= al0; lf[2] *= al1; lf[3] *= al1;
        }

        // ---- P = 2^(s - m) as fp16 pairs ----
        uint32_t pfr[8][2];
#pragma unroll
        for (int ni = 0; ni < 8; ++ni) {
            pfr[ni][0] = exp2_f16x2(sacc[ni][0] - mnew0, sacc[ni][1] - mnew0);
            pfr[ni][1] = exp2_f16x2(sacc[ni][2] - mnew1, sacc[ni][3] - mnew1);
        }

        // ---- l += P @ ones, O += P @ V ----
#pragma unroll
        for (int t = 0; t < 4; ++t) {
            uint32_t a[4] = { pfr[2 * t][0], pfr[2 * t][1],
                              pfr[2 * t + 1][0], pfr[2 * t + 1][1] };
            mma_f16(lf, a, ONESH2, ONESH2);
#pragma unroll
            for (int dnp = 0; dnp < 4; ++dnp) {
                const int tr = t * 16 + trow_l;
                uint32_t off = (uint32_t)(tr * 128 +
                               (((dnp * 2 + tchk_l) ^ (tr & 7)) * 16));
                uint32_t vv[4];
                ldsm4t(vv, VS + off);
                mma_f16(oacc[dnp * 2],     a, vv[0], vv[1]);
                mma_f16(oacc[dnp * 2 + 1], a, vv[2], vv[3]);
            }
        }
        __syncthreads();
    }

    // ---- normalize + fp16 output ----
    const float inv0 = 1.f / lf[0];
    const float inv1 = 1.f / lf[2];
    const int r0g = base + m0 + w * 16 + (lane >> 2);
    const int cq = (lane & 3) * 2;
#pragma unroll
    for (int ni = 0; ni < 8; ++ni) {
        const int col = hoff + ni * 8 + cq;
        *(__half2*)(Og + (size_t)r0g * DMODEL + col) =
            __floats2half2_rn(oacc[ni][0] * inv0, oacc[ni][1] * inv0);
        *(__half2*)(Og + (size_t)(r0g + 8) * DMODEL + col) =
            __floats2half2_rn(oacc[ni][2] * inv1, oacc[ni][3] * inv1);
    }
}

// ---------------------------------------------------------------------------
extern "C" void kernel_launch(void* const* d_in, const int* in_sizes, int n_in,
                              void* d_out, int out_size)
{
    const float* X  = (const float*)d_in[0];
    const float* Wq = (const float*)d_in[1];
    const float* bq = (const float*)d_in[2];
    const float* Wk = (const float*)d_in[3];
    const float* bk = (const float*)d_in[4];
    const float* Wv = (const float*)d_in[5];
    const float* bv = (const float*)d_in[6];
    const float* Wo = (const float*)d_in[7];
    const float* bo = (const float*)d_in[8];
    float* Y = (float*)d_out;

    __half *xf, *wf, *qh, *kh, *vh, *af;
    cudaGetSymbolAddress((void**)&xf, g_xf);
    cudaGetSymbolAddress((void**)&wf, g_wf);
    cudaGetSymbolAddress((void**)&qh, g_qh);
    cudaGetSymbolAddress((void**)&kh, g_kh);
    cudaGetSymbolAddress((void**)&vh, g_vh);
    cudaGetSymbolAddress((void**)&af, g_af);

    cudaFuncSetAttribute(gemm_f16<0>,
                         cudaFuncAttributeMaxDynamicSharedMemorySize, GEMMF_SMEM);
    cudaFuncSetAttribute(gemm_f16<1>,
                         cudaFuncAttributeMaxDynamicSharedMemorySize, GEMMF_SMEM);
    cudaFuncSetAttribute(attn_mma,
                         cudaFuncAttributeMaxDynamicSharedMemorySize, ATT_SMEM);

    const int XN4 = MROWS * DMODEL / 4;
    const int WN4 = DMODEL * DMODEL / 4;
    tofp16_kernel<<<XN4 / 256, 256>>>(X, xf, XN4);
    dim3 gw(WN4 / 256, 4);
    wconv4_kernel<<<gw, 256>>>(Wq, Wk, Wv, Wo, wf, WN4);

    // QKV projections -> fp16 (Q pre-scaled into log2 domain)
    dim3 gqkv(DMODEL / 128, MROWS / 128, 3);
    gemm_f16<1><<<gqkv, 256, GEMMF_SMEM>>>(xf, wf, bq, bk, bv,
                                           qh, kh, vh, nullptr, QSCALE);

    // flash attention (HMMA) -> fp16 output
    dim3 gattn(SEQ / 64, 1, NB * NH);
    attn_mma<<<gattn, 128, ATT_SMEM>>>(qh, kh, vh, af);

    // O projection (single fp16) -> fp32 Y
    dim3 go(DMODEL / 128, MROWS / 128, 1);
    gemm_f16<0><<<go, 256, GEMMF_SMEM>>>(af, wf + 3 * (size_t)DMODEL * DMODEL,
                                         bo, bo, bo,
                                         nullptr, nullptr, nullptr, Y, 1.0f);
}

// round 8
// speedup vs baseline: 7.5808x; 1.0330x over previous
#include <cuda_runtime.h>
#include <cuda_fp16.h>
#include <stdint.h>

#define SEQ    2048
#define DMODEL 1024
#define NH     16
#define HDIM   64
#define NB     2
#define MROWS  (NB * SEQ)   // 4096
#define GK     DMODEL

#define QSCALE 0.18033688011112042f   // 0.125 * log2(e)

// Scratch (device globals: no allocation allowed in kernel_launch)
__device__ __half g_xf[MROWS * DMODEL];
__device__ __half g_wf[4 * DMODEL * DMODEL];   // Wq, Wk, Wv, Wo (fp16)
__device__ __half g_qh[MROWS * DMODEL];
__device__ __half g_kh[MROWS * DMODEL];
__device__ __half g_vh[MROWS * DMODEL];
__device__ __half g_af[MROWS * DMODEL];        // attention output (fp16)

// ---------------------------------------------------------------------------
// helpers (all baseline PTX: sm_80-class, no 'a'-suffix features)
// ---------------------------------------------------------------------------
__device__ __forceinline__ uint32_t smem_u32(const void* p) {
    uint32_t a;
    asm("{ .reg .u64 t; cvta.to.shared.u64 t, %1; cvt.u32.u64 %0, t; }"
        : "=r"(a) : "l"(p));
    return a;
}

__device__ __forceinline__ void cp16(uint32_t s, const void* g) {
    asm volatile("cp.async.cg.shared.global [%0], [%1], 16;" :: "r"(s), "l"(g));
}

__device__ __forceinline__ void ldsm4(uint32_t* r, uint32_t a) {
    asm volatile("ldmatrix.sync.aligned.m8n8.x4.shared.b16 {%0,%1,%2,%3}, [%4];"
                 : "=r"(r[0]), "=r"(r[1]), "=r"(r[2]), "=r"(r[3]) : "r"(a));
}

__device__ __forceinline__ void ldsm4t(uint32_t* r, uint32_t a) {
    asm volatile("ldmatrix.sync.aligned.m8n8.x4.trans.shared.b16 {%0,%1,%2,%3}, [%4];"
                 : "=r"(r[0]), "=r"(r[1]), "=r"(r[2]), "=r"(r[3]) : "r"(a));
}

__device__ __forceinline__ void mma_f16(float* d, const uint32_t* a,
                                        uint32_t b0, uint32_t b1) {
    asm volatile(
        "mma.sync.aligned.m16n8k16.row.col.f32.f16.f16.f32 "
        "{%0,%1,%2,%3}, {%4,%5,%6,%7}, {%8,%9}, {%0,%1,%2,%3};"
        : "+f"(d[0]), "+f"(d[1]), "+f"(d[2]), "+f"(d[3])
        : "r"(a[0]), "r"(a[1]), "r"(a[2]), "r"(a[3]), "r"(b0), "r"(b1));
}

__device__ __forceinline__ float ex2f(float x) {
    float r;
    asm("ex2.approx.f32 %0, %1;" : "=f"(r) : "f"(x));
    return r;
}

// pack (lo,hi) to f16x2 then 2^x elementwise
__device__ __forceinline__ uint32_t exp2_f16x2(float lo, float hi) {
    uint32_t p, r;
    asm("cvt.rn.f16x2.f32 %0, %1, %2;" : "=r"(p) : "f"(hi), "f"(lo));
    asm("ex2.approx.f16x2 %0, %1;" : "=r"(r) : "r"(p));
    return r;
}

// ---------------------------------------------------------------------------
// fp32 -> fp16 convert: 4 float4 per thread, coalesced stride
// ---------------------------------------------------------------------------
__global__ __launch_bounds__(256) void tofp16_kernel(
    const float* __restrict__ in, __half* __restrict__ out, int stride4)
{
    int t = blockIdx.x * blockDim.x + threadIdx.x;
#pragma unroll
    for (int j = 0; j < 4; ++j) {
        int i = t + j * stride4;
        float4 v = ((const float4*)in)[i];
        ((__half2*)out)[2 * i]     = __floats2half2_rn(v.x, v.y);
        ((__half2*)out)[2 * i + 1] = __floats2half2_rn(v.z, v.w);
    }
}

// 4 weight matrices in one launch (blockIdx.y selects), 4 float4 per thread
__global__ __launch_bounds__(256) void wconv4_kernel(
    const float* __restrict__ w0, const float* __restrict__ w1,
    const float* __restrict__ w2, const float* __restrict__ w3,
    __half* __restrict__ out, int stride4)
{
    int t = blockIdx.x * blockDim.x + threadIdx.x;
    const int z = blockIdx.y;
    const float* in = (z == 0) ? w0 : ((z == 1) ? w1 : ((z == 2) ? w2 : w3));
    __half* o = out + (size_t)z * DMODEL * DMODEL;
#pragma unroll
    for (int j = 0; j < 4; ++j) {
        int i = t + j * stride4;
        float4 v = ((const float4*)in)[i];
        ((__half2*)o)[2 * i]     = __floats2half2_rn(v.x, v.y);
        ((__half2*)o)[2 * i + 1] = __floats2half2_rn(v.z, v.w);
    }
}

// ---------------------------------------------------------------------------
// Single-fp16 HMMA GEMM: Out[m][n] = sum_k A[m][k]*W[n][k] + bias[n]
// CTA 128x128, BK=64, cp.async double buffer, XOR-swizzled smem.
// OM==1: 3 weight sets (z selects), fp16 out, z==0 scaled.  OM==0: fp32 out.
// ---------------------------------------------------------------------------
#define GEMMF_SMEM (2 * 32768)

template<int OM>
__global__ __launch_bounds__(256, 2) void gemm_f16(
    const __half* __restrict__ A, const __half* __restrict__ Wb,
    const float* __restrict__ bias0, const float* __restrict__ bias1,
    const float* __restrict__ bias2,
    __half* __restrict__ o0, __half* __restrict__ o1, __half* __restrict__ o2,
    float* __restrict__ fo, float scale0)
{
    extern __shared__ char smem[];
    const int tid = threadIdx.x;
    const int z = (OM == 1) ? blockIdx.z : 0;
    const __half* W = Wb + (size_t)z * GK * GK;
    const float* bias = (z == 0) ? bias0 : ((z == 1) ? bias1 : bias2);
    const int m0 = blockIdx.y * 128, n0 = blockIdx.x * 128;

    const uint32_t sb = smem_u32(smem);
    const int lane = tid & 31, warp = tid >> 5;
    const int wm = warp & 1, wn = warp >> 1;   // warp tile 64x32

    const int lr = tid >> 1;
    const int lh = (tid & 1) * 4;
    const __half* gA = A + (size_t)(m0 + lr) * GK + lh * 8;
    const __half* gW = W + (size_t)(n0 + lr) * GK + lh * 8;
    const uint32_t lrow = (uint32_t)(lr * 128);
    const int lswz = lr & 7;

    const int arow = (lane & 7) + ((lane >> 3) & 1) * 8;
    const int akb  = lane >> 4;
    const int bnof = ((lane >> 4) << 3) + (lane & 7);
    const int bkb  = (lane >> 3) & 1;

    float acc[4][4][4];
#pragma unroll
    for (int i = 0; i < 4; i++)
#pragma unroll
        for (int j = 0; j < 4; j++)
#pragma unroll
            for (int t = 0; t < 4; t++) acc[i][j][t] = 0.f;

    {
        uint32_t base = sb + lrow;
#pragma unroll
        for (int j = 0; j < 4; ++j) {
            uint32_t sw = (uint32_t)(((lh + j) ^ lswz) * 16);
            cp16(base + sw,         gA + j * 8);
            cp16(base + 16384 + sw, gW + j * 8);
        }
        asm volatile("cp.async.commit_group;");
    }

    for (int c = 0; c < GK / 64; ++c) {
        if (c + 1 < GK / 64) {
            const int k0 = (c + 1) * 64;
            uint32_t base = sb + ((c + 1) & 1) * 32768 + lrow;
#pragma unroll
            for (int j = 0; j < 4; ++j) {
                uint32_t sw = (uint32_t)(((lh + j) ^ lswz) * 16);
                cp16(base + sw,         gA + k0 + j * 8);
                cp16(base + 16384 + sw, gW + k0 + j * 8);
            }
            asm volatile("cp.async.commit_group;");
            asm volatile("cp.async.wait_group 1;");
        } else {
            asm volatile("cp.async.commit_group;");
            asm volatile("cp.async.wait_group 0;");
        }
        __syncthreads();

        const uint32_t aS = sb + (c & 1) * 32768;
        const uint32_t wS = aS + 16384;

#pragma unroll
        for (int kk = 0; kk < 4; ++kk) {
            uint32_t bw[2][4];
#pragma unroll
            for (int nip = 0; nip < 2; ++nip) {
                int n = wn * 32 + nip * 16 + bnof;
                uint32_t off = (uint32_t)(n * 128 + (((kk * 2 + bkb) ^ (n & 7)) * 16));
                ldsm4(bw[nip], wS + off);
            }
#pragma unroll
            for (int mi = 0; mi < 4; ++mi) {
                int r = wm * 64 + mi * 16 + arow;
                uint32_t off = (uint32_t)(r * 128 + (((kk * 2 + akb) ^ (r & 7)) * 16));
                uint32_t af[4];
                ldsm4(af, aS + off);
#pragma unroll
                for (int ni = 0; ni < 4; ++ni) {
                    const int nip = ni >> 1, q = (ni & 1) * 2;
                    mma_f16(acc[mi][ni], af, bw[nip][q], bw[nip][q + 1]);
                }
            }
        }
        __syncthreads();
    }

    if (OM == 1) {
        __half* Out = (z == 0) ? o0 : ((z == 1) ? o1 : o2);
        const float cs = (z == 0) ? scale0 : 1.0f;
#pragma unroll
        for (int mi = 0; mi < 4; ++mi) {
            const int r0 = m0 + wm * 64 + mi * 16 + (lane >> 2);
#pragma unroll
            for (int ni = 0; ni < 4; ++ni) {
                const int c0 = n0 + wn * 32 + ni * 8 + (lane & 3) * 2;
                const float bv0 = bias[c0], bv1 = bias[c0 + 1];
                *(__half2*)(Out + (size_t)r0 * GK + c0) =
                    __floats2half2_rn((acc[mi][ni][0] + bv0) * cs,
                                      (acc[mi][ni][1] + bv1) * cs);
                *(__half2*)(Out + (size_t)(r0 + 8) * GK + c0) =
                    __floats2half2_rn((acc[mi][ni][2] + bv0) * cs,
                                      (acc[mi][ni][3] + bv1) * cs);
            }
        }
    } else {
#pragma unroll
        for (int mi = 0; mi < 4; ++mi) {
            const int r0 = m0 + wm * 64 + mi * 16 + (lane >> 2);
#pragma unroll
            for (int ni = 0; ni < 4; ++ni) {
                const int c0 = n0 + wn * 32 + ni * 8 + (lane & 3) * 2;
                const float bv0 = bias[c0], bv1 = bias[c0 + 1];
                fo[(size_t)r0 * GK + c0]           = acc[mi][ni][0] + bv0;
                fo[(size_t)r0 * GK + c0 + 1]       = acc[mi][ni][1] + bv1;
                fo[(size_t)(r0 + 8) * GK + c0]     = acc[mi][ni][2] + bv0;
                fo[(size_t)(r0 + 8) * GK + c0 + 1] = acc[mi][ni][3] + bv1;
            }
        }
    }
}

// ---------------------------------------------------------------------------
// HMMA causal flash attention, single-fp16 operands, log2-domain softmax.
// CTA: 64 q-rows x 64-key tiles, 4 warps.
// 4-stage KV ring (prefetch depth 2), ONE __syncthreads per iteration:
// writer of stage (j+2)&3 never collides with readers of stages (j-1)&3 / j&3.
// Smem: Q(8K) + 4 x {K(8K),V(8K)} = 72K.  Output: fp16.
// ---------------------------------------------------------------------------
#define ATT_SMEM (8192 + 4 * 16384)
#define ONESH2 0x3C003C00u

__global__ __launch_bounds__(128, 3) void attn_mma(
    const __half* __restrict__ Qg, const __half* __restrict__ Kg,
    const __half* __restrict__ Vg, __half* __restrict__ Og)
{
    extern __shared__ char smem[];
    const uint32_t sb = smem_u32(smem);
    const int tid = threadIdx.x;
    const int lane = tid & 31, w = tid >> 5;
    const int mt = (int)gridDim.x - 1 - (int)blockIdx.x;   // heavy tiles first
    const int bh = blockIdx.z;
    const int b = bh >> 4, h = bh & 15;
    const int m0 = mt * 64;
    const int base = b * SEQ;
    const int hoff = h * HDIM;

    const int lr = tid >> 1;
    const int lc4 = (tid & 1) * 4;
    const uint32_t lrow128 = (uint32_t)(lr * 128);
    const int lswz = lr & 7;
    const __half* gQ = Qg + (size_t)(base + m0 + lr) * DMODEL + hoff + lc4 * 8;
    const __half* gK = Kg + (size_t)(base + lr) * DMODEL + hoff + lc4 * 8;
    const __half* gV = Vg + (size_t)(base + lr) * DMODEL + hoff + lc4 * 8;

    const uint32_t QS = sb;
    const uint32_t KV0 = sb + 8192;

    // prologue: group1 = Q + KV stage 0, group2 = KV stage 1 (may be empty)
    {
#pragma unroll
        for (int j = 0; j < 4; ++j) {
            uint32_t sw = (uint32_t)(((lc4 + j) ^ lswz) * 16);
            cp16(QS + lrow128 + sw, gQ + j * 8);
            uint32_t st = KV0 + lrow128 + sw;
            cp16(st,        gK + j * 8);
            cp16(st + 8192, gV + j * 8);
        }
        asm volatile("cp.async.commit_group;");
        if (mt >= 1) {
            const size_t koff = (size_t)64 * DMODEL;
            uint32_t st = KV0 + 16384 + lrow128;
#pragma unroll
            for (int j = 0; j < 4; ++j) {
                uint32_t sw = (uint32_t)(((lc4 + j) ^ lswz) * 16);
                cp16(st + sw,        gK + koff + j * 8);
                cp16(st + 8192 + sw, gV + koff + j * 8);
            }
        }
        asm volatile("cp.async.commit_group;");
    }

    const int arow = (lane & 7) + ((lane >> 3) & 1) * 8;
    const int akb  = lane >> 4;
    const int bnof = ((lane >> 4) << 3) + (lane & 7);
    const int bkb  = (lane >> 3) & 1;
    const int trow_l = (lane & 7) + ((lane >> 3) & 1) * 8;
    const int tchk_l = lane >> 4;

    float oacc[8][4];
    float lf[4];
    float mrow[2] = { -1e30f, -1e30f };
#pragma unroll
    for (int i = 0; i < 8; ++i)
#pragma unroll
        for (int e = 0; e < 4; ++e) oacc[i][e] = 0.f;
#pragma unroll
    for (int e = 0; e < 4; ++e) lf[e] = 0.f;

    uint32_t qf[4][4];
    bool qloaded = false;

    for (int j = 0; j <= mt; ++j) {
        // prefetch stage j+2 (always commit 1 group/iter: groups stay countable)
        if (j + 2 <= mt) {
            const size_t koff = (size_t)(j + 2) * 64 * DMODEL;
            uint32_t st = KV0 + ((j + 2) & 3) * 16384 + lrow128;
#pragma unroll
            for (int jj = 0; jj < 4; ++jj) {
                uint32_t sw = (uint32_t)(((lc4 + jj) ^ lswz) * 16);
                cp16(st + sw,        gK + koff + jj * 8);
                cp16(st + 8192 + sw, gV + koff + jj * 8);
            }
        }
        asm volatile("cp.async.commit_group;");
        // committed so far: j+3 groups; stage j is group j+1 -> allow 2 pending
        asm volatile("cp.async.wait_group 2;");
        __syncthreads();

        if (!qloaded) {
#pragma unroll
            for (int kk = 0; kk < 4; ++kk) {
                const int qr = w * 16 + arow;
                uint32_t off = (uint32_t)(qr * 128 + (((kk * 2 + akb) ^ (qr & 7)) * 16));
                ldsm4(qf[kk], QS + off);
            }
            qloaded = true;
        }

        const uint32_t KS = KV0 + (j & 3) * 16384;
        const uint32_t VS = KS + 8192;

        // ---- S = Q K^T (log2-domain scores) ----
        float sacc[8][4];
#pragma unroll
        for (int i = 0; i < 8; ++i)
#pragma unroll
            for (int e = 0; e < 4; ++e) sacc[i][e] = 0.f;

#pragma unroll
        for (int kk = 0; kk < 4; ++kk) {
#pragma unroll
            for (int np = 0; np < 4; ++np) {
                const int nr = np * 16 + bnof;
                uint32_t off = (uint32_t)(nr * 128 + (((kk * 2 + bkb) ^ (nr & 7)) * 16));
                uint32_t bk[4];
                ldsm4(bk, KS + off);
                mma_f16(sacc[np * 2],     qf[kk], bk[0], bk[1]);
                mma_f16(sacc[np * 2 + 1], qf[kk], bk[2], bk[3]);
            }
        }

        // ---- causal mask on diagonal tile ----
        if (j == mt) {
            const int rl0 = w * 16 + (lane >> 2);
            const int cl0 = (lane & 3) * 2;
#pragma unroll
            for (int ni = 0; ni < 8; ++ni) {
#pragma unroll
                for (int e = 0; e < 4; ++e) {
                    int col = ni * 8 + cl0 + (e & 1);
                    int row = rl0 + ((e >> 1) << 3);
                    if (col > row) sacc[ni][e] = -1e30f;
                }
            }
        }

        // ---- online softmax (log2 domain) ----
        float mnew0, mnew1;
        {
            float mx0 = -1e30f, mx1 = -1e30f;
#pragma unroll
            for (int ni = 0; ni < 8; ++ni) {
                mx0 = fmaxf(mx0, fmaxf(sacc[ni][0], sacc[ni][1]));
                mx1 = fmaxf(mx1, fmaxf(sacc[ni][2], sacc[ni][3]));
            }
            mx0 = fmaxf(mx0, __shfl_xor_sync(0xffffffffu, mx0, 1));
            mx0 = fmaxf(mx0, __shfl_xor_sync(0xffffffffu, mx0, 2));
            mx1 = fmaxf(mx1, __shfl_xor_sync(0xffffffffu, mx1, 1));
            mx1 = fmaxf(mx1, __shfl_xor_sync(0xffffffffu, mx1, 2));
            mnew0 = fmaxf(mrow[0], mx0);
            mnew1 = fmaxf(mrow[1], mx1);
            float al0 = ex2f(mrow[0] - mnew0);
            float al1 = ex2f(mrow[1] - mnew1);
            mrow[0] = mnew0; mrow[1] = mnew1;
#pragma unroll
            for (int ni = 0; ni < 8; ++ni) {
                oacc[ni][0] *= al0; oacc[ni][1] *= al0;
                oacc[ni][2] *= al1; oacc[ni][3] *= al1;
            }
            lf[0] *= al0; lf[1] *= al0; lf[2] *= al1; lf[3] *= al1;
        }

        // ---- P = 2^(s - m) as fp16 pairs ----
        uint32_t pfr[8][2];
#pragma unroll
        for (int ni = 0; ni < 8; ++ni) {
            pfr[ni][0] = exp2_f16x2(sacc[ni][0] - mnew0, sacc[ni][1] - mnew0);
            pfr[ni][1] = exp2_f16x2(sacc[ni][2] - mnew1, sacc[ni][3] - mnew1);
        }

        // ---- l += P @ ones, O += P @ V ----
#pragma unroll
        for (int t = 0; t < 4; ++t) {
            uint32_t a[4] = { pfr[2 * t][0], pfr[2 * t][1],
                              pfr[2 * t + 1][0], pfr[2 * t + 1][1] };
            mma_f16(lf, a, ONESH2, ONESH2);
#pragma unroll
            for (int dnp = 0; dnp < 4; ++dnp) {
                const int tr = t * 16 + trow_l;
                uint32_t off = (uint32_t)(tr * 128 +
                               (((dnp * 2 + tchk_l) ^ (tr & 7)) * 16));
                uint32_t vv[4];
                ldsm4t(vv, VS + off);
                mma_f16(oacc[dnp * 2],     a, vv[0], vv[1]);
                mma_f16(oacc[dnp * 2 + 1], a, vv[2], vv[3]);
            }
        }
        // no trailing barrier: 4-stage ring guarantees no WAR on smem
    }

    // ---- normalize + fp16 output ----
    const float inv0 = 1.f / lf[0];
    const float inv1 = 1.f / lf[2];
    const int r0g = base + m0 + w * 16 + (lane >> 2);
    const int cq = (lane & 3) * 2;
#pragma unroll
    for (int ni = 0; ni < 8; ++ni) {
        const int col = hoff + ni * 8 + cq;
        *(__half2*)(Og + (size_t)r0g * DMODEL + col) =
            __floats2half2_rn(oacc[ni][0] * inv0, oacc[ni][1] * inv0);
        *(__half2*)(Og + (size_t)(r0g + 8) * DMODEL + col) =
            __floats2half2_rn(oacc[ni][2] * inv1, oacc[ni][3] * inv1);
    }
}

// ---------------------------------------------------------------------------
extern "C" void kernel_launch(void* const* d_in, const int* in_sizes, int n_in,
                              void* d_out, int out_size)
{
    const float* X  = (const float*)d_in[0];
    const float* Wq = (const float*)d_in[1];
    const float* bq = (const float*)d_in[2];
    const float* Wk = (const float*)d_in[3];
    const float* bk = (const float*)d_in[4];
    const float* Wv = (const float*)d_in[5];
    const float* bv = (const float*)d_in[6];
    const float* Wo = (const float*)d_in[7];
    const float* bo = (const float*)d_in[8];
    float* Y = (float*)d_out;

    __half *xf, *wf, *qh, *kh, *vh, *af;
    cudaGetSymbolAddress((void**)&xf, g_xf);
    cudaGetSymbolAddress((void**)&wf, g_wf);
    cudaGetSymbolAddress((void**)&qh, g_qh);
    cudaGetSymbolAddress((void**)&kh, g_kh);
    cudaGetSymbolAddress((void**)&vh, g_vh);
    cudaGetSymbolAddress((void**)&af, g_af);

    cudaFuncSetAttribute(gemm_f16<0>,
                         cudaFuncAttributeMaxDynamicSharedMemorySize, GEMMF_SMEM);
    cudaFuncSetAttribute(gemm_f16<1>,
                         cudaFuncAttributeMaxDynamicSharedMemorySize, GEMMF_SMEM);
    cudaFuncSetAttribute(attn_mma,
                         cudaFuncAttributeMaxDynamicSharedMemorySize, ATT_SMEM);

    const int XN4 = MROWS * DMODEL / 4;    // 1048576
    const int WN4 = DMODEL * DMODEL / 4;   // 262144
    // X: 262144 threads x 4 float4
    tofp16_kernel<<<XN4 / 4 / 256, 256>>>(X, xf, XN4 / 4);
    // W: 65536 threads x 4 float4 per matrix
    dim3 gw(WN4 / 4 / 256, 4);
    wconv4_kernel<<<gw, 256>>>(Wq, Wk, Wv, Wo, wf, WN4 / 4);

    // QKV projections -> fp16 (Q pre-scaled into log2 domain)
    dim3 gqkv(DMODEL / 128, MROWS / 128, 3);
    gemm_f16<1><<<gqkv, 256, GEMMF_SMEM>>>(xf, wf, bq, bk, bv,
                                           qh, kh, vh, nullptr, QSCALE);

    // flash attention (HMMA) -> fp16 output
    dim3 gattn(SEQ / 64, 1, NB * NH);
    attn_mma<<<gattn, 128, ATT_SMEM>>>(qh, kh, vh, af);

    // O projection (single fp16) -> fp32 Y
    dim3 go(DMODEL / 128, MROWS / 128, 1);
    gemm_f16<0><<<go, 256, GEMMF_SMEM>>>(af, wf + 3 * (size_t)DMODEL * DMODEL,
                                         bo, bo, bo,
                                         nullptr, nullptr, nullptr, Y, 1.0f);
}